// round 1
// baseline (speedup 1.0000x reference)
#include <cuda_runtime.h>
#include <math.h>

#define BB 2
#define NN 256
#define FF 64
#define HH 64
#define HEADS 4
#define CC 256
#define EPSV 1e-5f
#define INFV 1e5f

// ---------------- scratch (device globals; no allocations allowed) ----------
__device__ float g_e[BB*NN*NN*HH];          // edge MLP outputs   (32 MB)
__device__ float g_sem[BB*NN*NN*HEADS];     // leaky sem logits   (2 MB)
__device__ float g_att[BB*NN*NN*HEADS];     // combined attention (2 MB)
__device__ float g_xnorm[BB*NN*NN];         // pair distances
__device__ float g_combnorm[BB*NN*CC];
__device__ float g_hagg[BB*NN*CC];
__device__ float g_deltav[BB*NN*3];

__device__ __forceinline__ float silu_f(float x) { return x / (1.f + expf(-x)); }

// ---------------- kernel A: edge MLP + sem logits + distances ----------------
// grid: BB*NN*(NN/4) blocks, 256 threads; each block does 4 j's for one (b,i)
__global__ void edge_kernel(const float* __restrict__ h, const float* __restrict__ x,
                            const float* __restrict__ w1, const float* __restrict__ b1,
                            const float* __restrict__ w2, const float* __restrict__ b2,
                            const float* __restrict__ sw, const float* __restrict__ sb)
{
    int blk = blockIdx.x;
    int jg  = blk % (NN/4);
    int bi  = blk / (NN/4);
    int i   = bi % NN;
    int b   = bi / NN;
    int t   = threadIdx.x;
    int jl  = t >> 6;       // 0..3
    int k   = t & 63;       // 0..63
    int j   = jg*4 + jl;

    __shared__ float sh_hi[FF];
    __shared__ float sh_hj[4][FF];
    __shared__ float sh_hid[4][HH];
    __shared__ float sh_e[4][HH];
    __shared__ float sh_xn[4];

    if (jl == 0) sh_hi[k] = h[(b*NN + i)*FF + k];
    sh_hj[jl][k] = h[(b*NN + j)*FF + k];
    if (k == 0) {
        float dx = x[(b*NN + j)*3 + 0] - x[(b*NN + i)*3 + 0];
        float dy = x[(b*NN + j)*3 + 1] - x[(b*NN + i)*3 + 1];
        float dz = x[(b*NN + j)*3 + 2] - x[(b*NN + i)*3 + 2];
        float xn = sqrtf(dx*dx + dy*dy + dz*dz + EPSV);
        sh_xn[jl] = xn;
        g_xnorm[(b*NN + i)*NN + j] = xn;
    }
    __syncthreads();

    // layer 1: input = [h_j(64), h_i(64), x_norm]
    float acc = b1[k] + sh_xn[jl] * w1[128*HH + k];
    #pragma unroll 8
    for (int f = 0; f < FF; f++) {
        acc += sh_hj[jl][f] * w1[f*HH + k];
        acc += sh_hi[f]     * w1[(FF + f)*HH + k];
    }
    sh_hid[jl][k] = silu_f(acc);
    __syncthreads();

    // layer 2
    float acc2 = b2[k];
    #pragma unroll 8
    for (int m = 0; m < HH; m++) acc2 += sh_hid[jl][m] * w2[m*HH + k];
    float ev = silu_f(acc2);
    sh_e[jl][k] = ev;
    g_e[((b*NN + i)*NN + j)*HH + k] = ev;
    __syncthreads();

    // sem logits (leaky relu 0.2, pre-mask)
    if (k < HEADS) {
        float a = sb[k];
        #pragma unroll 8
        for (int m = 0; m < HH; m++) a += sh_e[jl][m] * sw[m*HEADS + k];
        a = (a > 0.f) ? a : 0.2f * a;
        g_sem[((b*NN + i)*NN + j)*HEADS + k] = a;
    }
}

// ---------------- block reductions (256 threads) -----------------------------
__device__ __forceinline__ float blk_max256(float v, float* red) {
    int t = threadIdx.x;
    red[t] = v; __syncthreads();
    for (int s = 128; s > 0; s >>= 1) {
        if (t < s) red[t] = fmaxf(red[t], red[t + s]);
        __syncthreads();
    }
    float r = red[0]; __syncthreads();
    return r;
}
__device__ __forceinline__ float blk_sum256(float v, float* red) {
    int t = threadIdx.x;
    red[t] = v; __syncthreads();
    for (int s = 128; s > 0; s >>= 1) {
        if (t < s) red[t] += red[t + s];
        __syncthreads();
    }
    float r = red[0]; __syncthreads();
    return r;
}

// ---------------- kernel B: triple softmax over j ---------------------------
// grid: BB*NN blocks, 256 threads (thread = j)
__global__ void att_kernel(const float* __restrict__ log_gamma)
{
    int b = blockIdx.x / NN;
    int i = blockIdx.x % NN;
    int j = threadIdx.x;
    __shared__ float red[256];

    float xn   = g_xnorm[(b*NN + i)*NN + j];
    float diag = (i == j) ? INFV : 0.f;

    for (int hd = 0; hd < HEADS; hd++) {
        float gamma = expf(log_gamma[hd]);
        // euclid softmax over j of -(xn+mask)*gamma
        float l1 = -(xn + diag) * gamma;
        float m1 = blk_max256(l1, red);
        float e1 = expf(l1 - m1);
        float s1 = blk_sum256(e1, red);
        float eu = e1 / s1;
        // semantic softmax
        float sl = g_sem[((b*NN + i)*NN + j)*HEADS + hd] - diag;
        float m2 = blk_max256(sl, red);
        float e2 = expf(sl - m2);
        float s2 = blk_sum256(e2, red);
        float se = e2 / s2;
        // combined softmax of product
        float p  = eu * se;
        float m3 = blk_max256(p, red);
        float e3 = expf(p - m3);
        float s3 = blk_sum256(e3, red);
        g_att[((b*NN + i)*NN + j)*HEADS + hd] = e3 / s3;
    }
}

// ---------------- kernel C: aggregation over j ------------------------------
// grid: BB*NN blocks, 256 threads (thread = c = hh*4+head)
__global__ void agg_kernel(const float* __restrict__ x, const float* __restrict__ vmix)
{
    int b = blockIdx.x / NN;
    int i = blockIdx.x % NN;
    int c = threadIdx.x;
    int hh = c >> 2;
    int hd = c & 3;

    __shared__ float sh_e[4][HH];
    __shared__ float sh_att[4][HEADS];
    __shared__ float sh_u[4][3];
    __shared__ float red[256];

    float agg = 0.f, cs0 = 0.f, cs1 = 0.f, cs2 = 0.f;
    int jl = c >> 6, kk = c & 63;

    for (int j0 = 0; j0 < NN; j0 += 4) {
        sh_e[jl][kk] = g_e[((b*NN + i)*NN + (j0 + jl))*HH + kk];
        if (c < 16)
            sh_att[c >> 2][c & 3] = g_att[((b*NN + i)*NN + (j0 + (c >> 2)))*HEADS + (c & 3)];
        if (c < 12) {
            int jj = c / 3, d = c % 3;
            float xn = g_xnorm[(b*NN + i)*NN + (j0 + jj)];
            sh_u[jj][d] = (x[(b*NN + (j0 + jj))*3 + d] - x[(b*NN + i)*3 + d]) / (xn + EPSV);
        }
        __syncthreads();
        #pragma unroll
        for (int q = 0; q < 4; q++) {
            float w = sh_e[q][hh] * sh_att[q][hd];
            agg += w;
            cs0 += w * sh_u[q][0];
            cs1 += w * sh_u[q][1];
            cs2 += w * sh_u[q][2];
        }
        __syncthreads();
    }

    const float inv_n = 1.f / (float)NN;
    cs0 *= inv_n; cs1 *= inv_n; cs2 *= inv_n;

    g_hagg[(b*NN + i)*CC + c]     = agg;
    g_combnorm[(b*NN + i)*CC + c] = cs0*cs0 + cs1*cs1 + cs2*cs2;

    float vm = vmix[c];
    float d0 = blk_sum256(vm * cs0, red);
    float d1 = blk_sum256(vm * cs1, red);
    float d2 = blk_sum256(vm * cs2, red);
    if (c == 0) {
        g_deltav[(b*NN + i)*3 + 0] = d0;
        g_deltav[(b*NN + i)*3 + 1] = d1;
        g_deltav[(b*NN + i)*3 + 2] = d2;
    }
}

// ---------------- kernel D: post/node/vel MLPs + outputs --------------------
// grid: BB*NN blocks, 64 threads
__global__ void node_kernel(const float* __restrict__ h, const float* __restrict__ x,
                            const float* __restrict__ v,
                            const float* __restrict__ pw1, const float* __restrict__ pb1,
                            const float* __restrict__ pw2, const float* __restrict__ pb2,
                            const float* __restrict__ nw1, const float* __restrict__ nb1,
                            const float* __restrict__ nw2, const float* __restrict__ nb2,
                            const float* __restrict__ vw1, const float* __restrict__ vb1,
                            const float* __restrict__ vw2,
                            float* __restrict__ out)
{
    int b = blockIdx.x / NN;
    int i = blockIdx.x % NN;
    int k = threadIdx.x;

    __shared__ float cn[CC], hagg[CC], sh_h[FF], hid[HH], hcomb[HH], hnew[FF];
    __shared__ float red[64];

    #pragma unroll
    for (int r = 0; r < 4; r++) {
        cn[k + 64*r]   = g_combnorm[(b*NN + i)*CC + k + 64*r];
        hagg[k + 64*r] = g_hagg[(b*NN + i)*CC + k + 64*r];
    }
    sh_h[k] = h[(b*NN + i)*FF + k];
    __syncthreads();

    // post MLP
    float a = pb1[k];
    for (int c2 = 0; c2 < CC; c2++) a += cn[c2] * pw1[c2*HH + k];
    hid[k] = silu_f(a);
    __syncthreads();
    a = pb2[k];
    #pragma unroll 8
    for (int m = 0; m < HH; m++) a += hid[m] * pw2[m*HH + k];
    hcomb[k] = silu_f(a);
    __syncthreads();

    // node MLP: input = [h(64), h_agg(256), h_comb(64)]
    a = nb1[k];
    #pragma unroll 8
    for (int f = 0; f < FF; f++)  a += sh_h[f]  * nw1[f*HH + k];
    for (int c2 = 0; c2 < CC; c2++) a += hagg[c2] * nw1[(FF + c2)*HH + k];
    #pragma unroll 8
    for (int m = 0; m < HH; m++)  a += hcomb[m] * nw1[(FF + CC + m)*HH + k];
    __syncthreads();             // everyone done reading hid from post layer
    hid[k] = silu_f(a);
    __syncthreads();
    a = nb2[k];
    #pragma unroll 8
    for (int m = 0; m < HH; m++) a += hid[m] * nw2[m*HH + k];
    float hn = sh_h[k] + silu_f(a);
    hnew[k] = hn;
    out[(b*NN + i)*FF + k] = hn;
    __syncthreads();

    // velocity scale: silu(h_new @ vw1 + vb1) @ vw2  (scalar)
    a = vb1[k];
    #pragma unroll 8
    for (int f = 0; f < FF; f++) a += hnew[f] * vw1[f*HH + k];
    red[k] = silu_f(a) * vw2[k];
    __syncthreads();
    for (int s = 32; s > 0; s >>= 1) {
        if (k < s) red[k] += red[k + s];
        __syncthreads();
    }
    float vscale = red[0];

    if (k < 3) {
        float vv = v[(b*NN + i)*3 + k];
        float vn = g_deltav[(b*NN + i)*3 + k] + vscale * vv;
        float xn = x[(b*NN + i)*3 + k] + vn;
        out[BB*NN*FF + (b*NN + i)*3 + k]            = xn;  // x_new
        out[BB*NN*FF + BB*NN*3 + (b*NN + i)*3 + k]  = vn;  // v_new
    }
}

// ---------------------------------------------------------------------------
extern "C" void kernel_launch(void* const* d_in, const int* in_sizes, int n_in,
                              void* d_out, int out_size)
{
    const float* h        = (const float*)d_in[0];
    const float* x        = (const float*)d_in[1];
    const float* v        = (const float*)d_in[2];
    const float* edge_w1  = (const float*)d_in[3];
    const float* edge_b1  = (const float*)d_in[4];
    const float* edge_w2  = (const float*)d_in[5];
    const float* edge_b2  = (const float*)d_in[6];
    const float* sem_w    = (const float*)d_in[7];
    const float* sem_b    = (const float*)d_in[8];
    const float* post_w1  = (const float*)d_in[9];
    const float* post_b1  = (const float*)d_in[10];
    const float* post_w2  = (const float*)d_in[11];
    const float* post_b2  = (const float*)d_in[12];
    const float* node_w1  = (const float*)d_in[13];
    const float* node_b1  = (const float*)d_in[14];
    const float* node_w2  = (const float*)d_in[15];
    const float* node_b2  = (const float*)d_in[16];
    const float* vel_w1   = (const float*)d_in[17];
    const float* vel_b1   = (const float*)d_in[18];
    const float* vel_w2   = (const float*)d_in[19];
    const float* vmix_w   = (const float*)d_in[20];
    const float* log_gamma= (const float*)d_in[21];
    float* out = (float*)d_out;

    edge_kernel<<<BB*NN*(NN/4), 256>>>(h, x, edge_w1, edge_b1, edge_w2, edge_b2, sem_w, sem_b);
    att_kernel<<<BB*NN, 256>>>(log_gamma);
    agg_kernel<<<BB*NN, 256>>>(x, vmix_w);
    node_kernel<<<BB*NN, 64>>>(h, x, v,
                               post_w1, post_b1, post_w2, post_b2,
                               node_w1, node_b1, node_w2, node_b2,
                               vel_w1, vel_b1, vel_w2, out);
}

// round 2
// speedup vs baseline: 2.3239x; 2.3239x over previous
#include <cuda_runtime.h>
#include <math.h>

#define BB 2
#define NN 256
#define FF 64
#define HH 64
#define HEADS 4
#define CC 256
#define EPSV 1e-5f
#define INFV 1e5f
#define PADJ 68

typedef unsigned long long u64;

// ---------------- scratch (device globals) ----------------------------------
__device__ float g_e[BB*NN*NN*HH];
__device__ float g_sem[BB*NN*NN*HEADS];
__device__ float g_att[BB*NN*NN*HEADS];
__device__ float g_xnorm[BB*NN*NN];
__device__ float g_combnorm[BB*NN*CC];
__device__ float g_hagg[BB*NN*CC];
__device__ float g_deltav[BB*NN*3];

__device__ __forceinline__ float silu_f(float v){ return __fdividef(v, 1.f + __expf(-v)); }

__device__ __forceinline__ u64 pack2(float lo, float hi){
    u64 r; unsigned lu = __float_as_uint(lo), hu = __float_as_uint(hi);
    asm("mov.b64 %0, {%1, %2};" : "=l"(r) : "r"(lu), "r"(hu));
    return r;
}
__device__ __forceinline__ float2 unpack2(u64 v){
    unsigned lu, hu;
    asm("mov.b64 {%0, %1}, %2;" : "=r"(lu), "=r"(hu) : "l"(v));
    return make_float2(__uint_as_float(lu), __uint_as_float(hu));
}
#define FMA2(acc,a,b) asm("fma.rn.f32x2 %0, %1, %2, %3;" : "=l"(acc) : "l"(a), "l"(b), "l"(acc))

// ---------------- kernel A: edge MLP + sem logits + distances ----------------
// grid: BB*NN blocks (one per (b,i)), 256 threads. Register-tiled 4x4 GEMM.
__global__ __launch_bounds__(256) void edge_kernel(
        const float* __restrict__ h, const float* __restrict__ x,
        const float* __restrict__ w1, const float* __restrict__ b1,
        const float* __restrict__ w2, const float* __restrict__ b2,
        const float* __restrict__ sw, const float* __restrict__ sb)
{
    int bi = blockIdx.x;
    int b = bi >> 8, i = bi & 255;
    int t = threadIdx.x;
    int tx = t & 15, ty = t >> 4;

    __shared__ float hjT[64*PADJ];   // [f][j]  (reused as sem partials)
    __shared__ float hidT[64*PADJ];  // [k][j]
    __shared__ float acci_s[64];
    __shared__ float w1x_s[64];
    __shared__ float hi_s[64];
    __shared__ float xnorm_s[256];
    __shared__ float ssw[64*4];
    __shared__ float ssb[4];

    // ---- per-block setup ----
    if (t < 64) { hi_s[t] = h[(b*NN + i)*FF + t]; w1x_s[t] = w1[128*HH + t]; }
    {
        float dx = x[(b*NN + t)*3+0] - x[(b*NN + i)*3+0];
        float dy = x[(b*NN + t)*3+1] - x[(b*NN + i)*3+1];
        float dz = x[(b*NN + t)*3+2] - x[(b*NN + i)*3+2];
        float xn = sqrtf(dx*dx + dy*dy + dz*dz + EPSV);
        xnorm_s[t] = xn;
        g_xnorm[bi*NN + t] = xn;
        ssw[t] = sw[t];
    }
    if (t < 4) ssb[t] = sb[t];
    __syncthreads();

    // acci = b1 + h_i @ w1[64:128]   (shared by every j of this i)
    {
        int k = t & 63, r = t >> 6;
        float a = 0.f;
        #pragma unroll
        for (int f = 0; f < 16; f++)
            a += hi_s[16*r+f] * __ldg(&w1[(64 + 16*r + f)*HH + k]);
        hidT[r*64 + k] = a;
        __syncthreads();
        if (r == 0)
            acci_s[k] = b1[k] + hidT[k] + hidT[64+k] + hidT[128+k] + hidT[192+k];
        __syncthreads();
    }

    for (int jt = 0; jt < 4; jt++) {
        int j0 = jt*64;
        __syncthreads();  // protect sempart (hjT) reads of previous tile
        // load transposed activation tile: hjT[f][j] = h[b, j0+j, f]
        for (int idx = t; idx < 64*64; idx += 256) {
            int jl = idx >> 6, f = idx & 63;
            hjT[f*PADJ + jl] = h[(b*NN + j0 + jl)*FF + f];
        }
        __syncthreads();

        // ---- layer 1 ----
        u64 acc[4][2];
        {
            float4 ai = *(float4*)&acci_s[tx*4];
            float4 wx = *(float4*)&w1x_s[tx*4];
            #pragma unroll
            for (int jj = 0; jj < 4; jj++) {
                float xn = xnorm_s[j0 + ty*4 + jj];
                acc[jj][0] = pack2(ai.x + xn*wx.x, ai.y + xn*wx.y);
                acc[jj][1] = pack2(ai.z + xn*wx.z, ai.w + xn*wx.w);
            }
        }
        #pragma unroll 4
        for (int f = 0; f < 64; f++) {
            float4 wv = *(const float4*)&w1[f*HH + tx*4];
            float4 av = *(float4*)&hjT[f*PADJ + ty*4];
            u64 w01 = pack2(wv.x, wv.y), w23 = pack2(wv.z, wv.w);
            u64 a;
            a = pack2(av.x, av.x); FMA2(acc[0][0],a,w01); FMA2(acc[0][1],a,w23);
            a = pack2(av.y, av.y); FMA2(acc[1][0],a,w01); FMA2(acc[1][1],a,w23);
            a = pack2(av.z, av.z); FMA2(acc[2][0],a,w01); FMA2(acc[2][1],a,w23);
            a = pack2(av.w, av.w); FMA2(acc[3][0],a,w01); FMA2(acc[3][1],a,w23);
        }
        #pragma unroll
        for (int jj = 0; jj < 4; jj++) {
            float2 p0 = unpack2(acc[jj][0]), p1 = unpack2(acc[jj][1]);
            hidT[(tx*4+0)*PADJ + ty*4+jj] = silu_f(p0.x);
            hidT[(tx*4+1)*PADJ + ty*4+jj] = silu_f(p0.y);
            hidT[(tx*4+2)*PADJ + ty*4+jj] = silu_f(p1.x);
            hidT[(tx*4+3)*PADJ + ty*4+jj] = silu_f(p1.y);
        }
        __syncthreads();

        // ---- layer 2 ----
        float eb[4][4];
        {
            u64 acc2[4][2];
            float4 bv = *(const float4*)&b2[tx*4];
            #pragma unroll
            for (int jj = 0; jj < 4; jj++) {
                acc2[jj][0] = pack2(bv.x, bv.y);
                acc2[jj][1] = pack2(bv.z, bv.w);
            }
            #pragma unroll 4
            for (int kf = 0; kf < 64; kf++) {
                float4 wv = *(const float4*)&w2[kf*HH + tx*4];
                float4 av = *(float4*)&hidT[kf*PADJ + ty*4];
                u64 w01 = pack2(wv.x, wv.y), w23 = pack2(wv.z, wv.w);
                u64 a;
                a = pack2(av.x, av.x); FMA2(acc2[0][0],a,w01); FMA2(acc2[0][1],a,w23);
                a = pack2(av.y, av.y); FMA2(acc2[1][0],a,w01); FMA2(acc2[1][1],a,w23);
                a = pack2(av.z, av.z); FMA2(acc2[2][0],a,w01); FMA2(acc2[2][1],a,w23);
                a = pack2(av.w, av.w); FMA2(acc2[3][0],a,w01); FMA2(acc2[3][1],a,w23);
            }
            #pragma unroll
            for (int jj = 0; jj < 4; jj++) {
                float2 p0 = unpack2(acc2[jj][0]), p1 = unpack2(acc2[jj][1]);
                eb[jj][0] = silu_f(p0.x); eb[jj][1] = silu_f(p0.y);
                eb[jj][2] = silu_f(p1.x); eb[jj][3] = silu_f(p1.y);
            }
        }
        // store e to global (coalesced float4)
        #pragma unroll
        for (int jj = 0; jj < 4; jj++) {
            float4 ev = make_float4(eb[jj][0], eb[jj][1], eb[jj][2], eb[jj][3]);
            *(float4*)&g_e[(bi*NN + j0 + ty*4 + jj)*HH + tx*4] = ev;
        }

        // ---- sem logits: partials over k (split by tx), reduce in smem ----
        float* sempart = hjT;  // [16][64][4], safe: hjT dead after layer-1 sync
        #pragma unroll
        for (int jj = 0; jj < 4; jj++) {
            float p0=0.f, p1=0.f, p2=0.f, p3=0.f;
            #pragma unroll
            for (int kk = 0; kk < 4; kk++) {
                float e = eb[jj][kk];
                const float* swr = &ssw[(tx*4+kk)*4];
                p0 += e*swr[0]; p1 += e*swr[1]; p2 += e*swr[2]; p3 += e*swr[3];
            }
            float* dst = &sempart[(tx*64 + ty*4+jj)*4];
            dst[0]=p0; dst[1]=p1; dst[2]=p2; dst[3]=p3;
        }
        __syncthreads();
        {
            int jl = t >> 2, hd = t & 3;
            float a = ssb[hd];
            #pragma unroll
            for (int r = 0; r < 16; r++) a += sempart[(r*64 + jl)*4 + hd];
            a = (a > 0.f) ? a : 0.2f*a;
            g_sem[(bi*NN + j0 + jl)*HEADS + hd] = a;
        }
    }
}

// ---------------- warp/block reductions --------------------------------------
__device__ __forceinline__ float warpmaxf(float v){
    #pragma unroll
    for (int s=16;s;s>>=1) v = fmaxf(v, __shfl_xor_sync(0xffffffffu, v, s));
    return v;
}
__device__ __forceinline__ float warpsumf(float v){
    #pragma unroll
    for (int s=16;s;s>>=1) v += __shfl_xor_sync(0xffffffffu, v, s);
    return v;
}
__device__ __forceinline__ float4 blk_reduce4(float4 v, bool is_max, float4* redbuf){
    if (is_max) { v.x=warpmaxf(v.x); v.y=warpmaxf(v.y); v.z=warpmaxf(v.z); v.w=warpmaxf(v.w); }
    else        { v.x=warpsumf(v.x); v.y=warpsumf(v.y); v.z=warpsumf(v.z); v.w=warpsumf(v.w); }
    int w = threadIdx.x>>5, l = threadIdx.x&31;
    if (l == 0) redbuf[w] = v;
    __syncthreads();
    float4 r = redbuf[0];
    #pragma unroll
    for (int q = 1; q < 8; q++) {
        float4 o = redbuf[q];
        if (is_max) { r.x=fmaxf(r.x,o.x); r.y=fmaxf(r.y,o.y); r.z=fmaxf(r.z,o.z); r.w=fmaxf(r.w,o.w); }
        else        { r.x+=o.x; r.y+=o.y; r.z+=o.z; r.w+=o.w; }
    }
    __syncthreads();
    return r;
}

// ---------------- kernel B: triple softmax over j, 4 heads vectorized -------
__global__ __launch_bounds__(256) void att_kernel(const float* __restrict__ log_gamma)
{
    __shared__ float4 redbuf[8];
    int bi = blockIdx.x;
    int i = bi & 255;
    int j = threadIdx.x;

    float4 lg = *(const float4*)log_gamma;
    float4 gm = make_float4(__expf(lg.x), __expf(lg.y), __expf(lg.z), __expf(lg.w));

    float xn = g_xnorm[bi*NN + j];
    float diag = (j == i) ? INFV : 0.f;
    float xm = xn + diag;

    // euclid softmax
    float4 l1 = make_float4(-xm*gm.x, -xm*gm.y, -xm*gm.z, -xm*gm.w);
    float4 m1 = blk_reduce4(l1, true, redbuf);
    float4 e1 = make_float4(__expf(l1.x-m1.x), __expf(l1.y-m1.y), __expf(l1.z-m1.z), __expf(l1.w-m1.w));
    float4 s1 = blk_reduce4(e1, false, redbuf);
    float4 eu = make_float4(__fdividef(e1.x,s1.x), __fdividef(e1.y,s1.y),
                            __fdividef(e1.z,s1.z), __fdividef(e1.w,s1.w));
    // semantic softmax
    float4 sl = *(const float4*)&g_sem[(bi*NN + j)*HEADS];
    sl.x -= diag; sl.y -= diag; sl.z -= diag; sl.w -= diag;
    float4 m2 = blk_reduce4(sl, true, redbuf);
    float4 e2 = make_float4(__expf(sl.x-m2.x), __expf(sl.y-m2.y), __expf(sl.z-m2.z), __expf(sl.w-m2.w));
    float4 s2 = blk_reduce4(e2, false, redbuf);
    float4 se = make_float4(__fdividef(e2.x,s2.x), __fdividef(e2.y,s2.y),
                            __fdividef(e2.z,s2.z), __fdividef(e2.w,s2.w));
    // combined softmax of product
    float4 p = make_float4(eu.x*se.x, eu.y*se.y, eu.z*se.z, eu.w*se.w);
    float4 m3 = blk_reduce4(p, true, redbuf);
    float4 e3 = make_float4(__expf(p.x-m3.x), __expf(p.y-m3.y), __expf(p.z-m3.z), __expf(p.w-m3.w));
    float4 s3 = blk_reduce4(e3, false, redbuf);
    float4 att = make_float4(__fdividef(e3.x,s3.x), __fdividef(e3.y,s3.y),
                             __fdividef(e3.z,s3.z), __fdividef(e3.w,s3.w));
    *(float4*)&g_att[(bi*NN + j)*HEADS] = att;
}

// ---------------- kernel C: aggregation over j ------------------------------
__device__ __forceinline__ float blk_sum256(float v, float* red) {
    int t = threadIdx.x;
    red[t] = v; __syncthreads();
    for (int s = 128; s > 0; s >>= 1) {
        if (t < s) red[t] += red[t + s];
        __syncthreads();
    }
    float r = red[0]; __syncthreads();
    return r;
}

__global__ __launch_bounds__(256) void agg_kernel(const float* __restrict__ x, const float* __restrict__ vmix)
{
    int bi = blockIdx.x;
    int b = bi >> 8, i = bi & 255;
    int c = threadIdx.x;
    int hh = c >> 2;
    int hd = c & 3;

    __shared__ float sh_e[4][HH];
    __shared__ float sh_att[4][HEADS];
    __shared__ float sh_u[4][3];
    __shared__ float red[256];

    float agg = 0.f, cs0 = 0.f, cs1 = 0.f, cs2 = 0.f;
    int jl = c >> 6, kk = c & 63;

    for (int j0 = 0; j0 < NN; j0 += 4) {
        sh_e[jl][kk] = g_e[(bi*NN + (j0 + jl))*HH + kk];
        if (c < 16)
            sh_att[c >> 2][c & 3] = g_att[(bi*NN + (j0 + (c >> 2)))*HEADS + (c & 3)];
        if (c < 12) {
            int jj = c / 3, d = c % 3;
            float xn = g_xnorm[bi*NN + (j0 + jj)];
            sh_u[jj][d] = __fdividef(x[(b*NN + (j0 + jj))*3 + d] - x[(b*NN + i)*3 + d], xn + EPSV);
        }
        __syncthreads();
        #pragma unroll
        for (int q = 0; q < 4; q++) {
            float w = sh_e[q][hh] * sh_att[q][hd];
            agg += w;
            cs0 += w * sh_u[q][0];
            cs1 += w * sh_u[q][1];
            cs2 += w * sh_u[q][2];
        }
        __syncthreads();
    }

    const float inv_n = 1.f / (float)NN;
    cs0 *= inv_n; cs1 *= inv_n; cs2 *= inv_n;

    g_hagg[bi*CC + c]     = agg;
    g_combnorm[bi*CC + c] = cs0*cs0 + cs1*cs1 + cs2*cs2;

    float vm = vmix[c];
    float d0 = blk_sum256(vm * cs0, red);
    float d1 = blk_sum256(vm * cs1, red);
    float d2 = blk_sum256(vm * cs2, red);
    if (c == 0) {
        g_deltav[bi*3 + 0] = d0;
        g_deltav[bi*3 + 1] = d1;
        g_deltav[bi*3 + 2] = d2;
    }
}

// ---------------- kernel D: post/node/vel MLPs + outputs --------------------
// grid: BB*NN blocks, 256 threads (64 k x 4 reduction splits)
__global__ __launch_bounds__(256) void node_kernel(
        const float* __restrict__ h, const float* __restrict__ x,
        const float* __restrict__ v,
        const float* __restrict__ pw1, const float* __restrict__ pb1,
        const float* __restrict__ pw2, const float* __restrict__ pb2,
        const float* __restrict__ nw1, const float* __restrict__ nb1,
        const float* __restrict__ nw2, const float* __restrict__ nb2,
        const float* __restrict__ vw1, const float* __restrict__ vb1,
        const float* __restrict__ vw2,
        float* __restrict__ out)
{
    int bi = blockIdx.x;
    int t = threadIdx.x;
    int k = t & 63, r = t >> 6;

    __shared__ float cn[CC], hagg[CC], sh_h[FF], hid[HH], hcomb[HH], hnew[FF];
    __shared__ float buf[4][64];
    __shared__ float vsc[1];

    cn[t]   = g_combnorm[bi*CC + t];
    hagg[t] = g_hagg[bi*CC + t];
    if (t < 64) sh_h[t] = h[bi*FF + t];
    __syncthreads();

    // post MLP layer 1 (K=256 split 4 ways)
    float a = 0.f;
    #pragma unroll 8
    for (int c2 = 64*r; c2 < 64*r + 64; c2++) a += cn[c2] * __ldg(&pw1[c2*HH + k]);
    buf[r][k] = a; __syncthreads();
    if (r == 0) hid[k] = silu_f(buf[0][k]+buf[1][k]+buf[2][k]+buf[3][k] + pb1[k]);
    __syncthreads();
    // post MLP layer 2
    a = 0.f;
    #pragma unroll
    for (int m = 16*r; m < 16*r + 16; m++) a += hid[m] * __ldg(&pw2[m*HH + k]);
    buf[r][k] = a; __syncthreads();
    if (r == 0) hcomb[k] = silu_f(buf[0][k]+buf[1][k]+buf[2][k]+buf[3][k] + pb2[k]);
    __syncthreads();

    // node MLP layer 1 (K=384 split 4 ways: [h(64), hagg(256), hcomb(64)])
    a = 0.f;
    for (int u = 96*r; u < 96*r + 96; u++) {
        float iv = (u < 64) ? sh_h[u] : ((u < 320) ? hagg[u-64] : hcomb[u-320]);
        a += iv * __ldg(&nw1[u*HH + k]);
    }
    buf[r][k] = a; __syncthreads();
    if (r == 0) hid[k] = silu_f(buf[0][k]+buf[1][k]+buf[2][k]+buf[3][k] + nb1[k]);
    __syncthreads();
    // node MLP layer 2 + residual
    a = 0.f;
    #pragma unroll
    for (int m = 16*r; m < 16*r + 16; m++) a += hid[m] * __ldg(&nw2[m*HH + k]);
    buf[r][k] = a; __syncthreads();
    if (r == 0) {
        float hn = sh_h[k] + silu_f(buf[0][k]+buf[1][k]+buf[2][k]+buf[3][k] + nb2[k]);
        hnew[k] = hn;
        out[bi*FF + k] = hn;
    }
    __syncthreads();

    // velocity scale
    a = 0.f;
    #pragma unroll
    for (int f = 16*r; f < 16*r + 16; f++) a += hnew[f] * __ldg(&vw1[f*HH + k]);
    buf[r][k] = a; __syncthreads();
    if (t < 32) {
        float s0 = silu_f(buf[0][t]+buf[1][t]+buf[2][t]+buf[3][t] + vb1[t]) * vw2[t];
        int t2 = t + 32;
        float s1 = silu_f(buf[0][t2]+buf[1][t2]+buf[2][t2]+buf[3][t2] + vb1[t2]) * vw2[t2];
        float s = warpsumf(s0 + s1);
        if (t == 0) vsc[0] = s;
    }
    __syncthreads();
    float vscale = vsc[0];

    if (t < 3) {
        float vv = v[bi*3 + t];
        float vn = g_deltav[bi*3 + t] + vscale * vv;
        out[BB*NN*FF + bi*3 + t]             = x[bi*3 + t] + vn;  // x_new
        out[BB*NN*FF + BB*NN*3 + bi*3 + t]   = vn;                // v_new
    }
}

// ---------------------------------------------------------------------------
extern "C" void kernel_launch(void* const* d_in, const int* in_sizes, int n_in,
                              void* d_out, int out_size)
{
    const float* h        = (const float*)d_in[0];
    const float* x        = (const float*)d_in[1];
    const float* v        = (const float*)d_in[2];
    const float* edge_w1  = (const float*)d_in[3];
    const float* edge_b1  = (const float*)d_in[4];
    const float* edge_w2  = (const float*)d_in[5];
    const float* edge_b2  = (const float*)d_in[6];
    const float* sem_w    = (const float*)d_in[7];
    const float* sem_b    = (const float*)d_in[8];
    const float* post_w1  = (const float*)d_in[9];
    const float* post_b1  = (const float*)d_in[10];
    const float* post_w2  = (const float*)d_in[11];
    const float* post_b2  = (const float*)d_in[12];
    const float* node_w1  = (const float*)d_in[13];
    const float* node_b1  = (const float*)d_in[14];
    const float* node_w2  = (const float*)d_in[15];
    const float* node_b2  = (const float*)d_in[16];
    const float* vel_w1   = (const float*)d_in[17];
    const float* vel_b1   = (const float*)d_in[18];
    const float* vel_w2   = (const float*)d_in[19];
    const float* vmix_w   = (const float*)d_in[20];
    const float* log_gamma= (const float*)d_in[21];
    float* out = (float*)d_out;

    edge_kernel<<<BB*NN, 256>>>(h, x, edge_w1, edge_b1, edge_w2, edge_b2, sem_w, sem_b);
    att_kernel<<<BB*NN, 256>>>(log_gamma);
    agg_kernel<<<BB*NN, 256>>>(x, vmix_w);
    node_kernel<<<BB*NN, 256>>>(h, x, v,
                                post_w1, post_b1, post_w2, post_b2,
                                node_w1, node_b1, node_w2, node_b2,
                                vel_w1, vel_b1, vel_w2, out);
}

// round 3
// speedup vs baseline: 2.6354x; 1.1341x over previous
#include <cuda_runtime.h>
#include <math.h>

#define BB 2
#define NN 256
#define FF 64
#define HH 64
#define HEADS 4
#define CC 256
#define EPSV 1e-5f
#define INFV 1e5f
#define PADJ 68

typedef unsigned long long u64;

// ---------------- scratch (device globals) ----------------------------------
__device__ float g_eT[BB*NN*HH*NN];         // transposed: [bi][h][j]
__device__ float g_sem[BB*NN*NN*HEADS];
__device__ float g_xnorm[BB*NN*NN];
__device__ float g_combnorm[BB*NN*CC];
__device__ float g_hagg[BB*NN*CC];
__device__ float g_deltav[BB*NN*3];

__device__ __forceinline__ float silu_f(float v){ return __fdividef(v, 1.f + __expf(-v)); }

__device__ __forceinline__ u64 pack2(float lo, float hi){
    u64 r; unsigned lu = __float_as_uint(lo), hu = __float_as_uint(hi);
    asm("mov.b64 %0, {%1, %2};" : "=l"(r) : "r"(lu), "r"(hu));
    return r;
}
__device__ __forceinline__ float2 unpack2(u64 v){
    unsigned lu, hu;
    asm("mov.b64 {%0, %1}, %2;" : "=r"(lu), "=r"(hu) : "l"(v));
    return make_float2(__uint_as_float(lu), __uint_as_float(hu));
}
#define FMA2(acc,a,b) asm("fma.rn.f32x2 %0, %1, %2, %3;" : "=l"(acc) : "l"(a), "l"(b), "l"(acc))

// ---------------- kernel A: edge MLP + sem logits + distances ----------------
__global__ __launch_bounds__(256) void edge_kernel(
        const float* __restrict__ h, const float* __restrict__ x,
        const float* __restrict__ w1, const float* __restrict__ b1,
        const float* __restrict__ w2, const float* __restrict__ b2,
        const float* __restrict__ sw, const float* __restrict__ sb)
{
    int bi = blockIdx.x;
    int b = bi >> 8, i = bi & 255;
    int t = threadIdx.x;
    int tx = t & 15, ty = t >> 4;

    __shared__ float hjT[64*PADJ];   // [f][j]  (reused as sem partials)
    __shared__ float hidT[64*PADJ];  // [k][j]
    __shared__ float acci_s[64];
    __shared__ float w1x_s[64];
    __shared__ float hi_s[64];
    __shared__ float xnorm_s[256];
    __shared__ float ssw[64*4];
    __shared__ float ssb[4];

    if (t < 64) { hi_s[t] = h[(b*NN + i)*FF + t]; w1x_s[t] = w1[128*HH + t]; }
    {
        float dx = x[(b*NN + t)*3+0] - x[(b*NN + i)*3+0];
        float dy = x[(b*NN + t)*3+1] - x[(b*NN + i)*3+1];
        float dz = x[(b*NN + t)*3+2] - x[(b*NN + i)*3+2];
        float xn = sqrtf(dx*dx + dy*dy + dz*dz + EPSV);
        xnorm_s[t] = xn;
        g_xnorm[bi*NN + t] = xn;
        ssw[t] = sw[t];
    }
    if (t < 4) ssb[t] = sb[t];
    __syncthreads();

    {   // acci = b1 + h_i @ w1[64:128]
        int k = t & 63, r = t >> 6;
        float a = 0.f;
        #pragma unroll
        for (int f = 0; f < 16; f++)
            a += hi_s[16*r+f] * __ldg(&w1[(64 + 16*r + f)*HH + k]);
        hidT[r*64 + k] = a;
        __syncthreads();
        if (r == 0)
            acci_s[k] = b1[k] + hidT[k] + hidT[64+k] + hidT[128+k] + hidT[192+k];
        __syncthreads();
    }

    for (int jt = 0; jt < 4; jt++) {
        int j0 = jt*64;
        __syncthreads();
        for (int idx = t; idx < 64*64; idx += 256) {
            int jl = idx >> 6, f = idx & 63;
            hjT[f*PADJ + jl] = h[(b*NN + j0 + jl)*FF + f];
        }
        __syncthreads();

        // ---- layer 1 ----
        u64 acc[4][2];
        {
            float4 ai = *(float4*)&acci_s[tx*4];
            float4 wx = *(float4*)&w1x_s[tx*4];
            #pragma unroll
            for (int jj = 0; jj < 4; jj++) {
                float xn = xnorm_s[j0 + ty*4 + jj];
                acc[jj][0] = pack2(ai.x + xn*wx.x, ai.y + xn*wx.y);
                acc[jj][1] = pack2(ai.z + xn*wx.z, ai.w + xn*wx.w);
            }
        }
        #pragma unroll 4
        for (int f = 0; f < 64; f++) {
            float4 wv = *(const float4*)&w1[f*HH + tx*4];
            float4 av = *(float4*)&hjT[f*PADJ + ty*4];
            u64 w01 = pack2(wv.x, wv.y), w23 = pack2(wv.z, wv.w);
            u64 a;
            a = pack2(av.x, av.x); FMA2(acc[0][0],a,w01); FMA2(acc[0][1],a,w23);
            a = pack2(av.y, av.y); FMA2(acc[1][0],a,w01); FMA2(acc[1][1],a,w23);
            a = pack2(av.z, av.z); FMA2(acc[2][0],a,w01); FMA2(acc[2][1],a,w23);
            a = pack2(av.w, av.w); FMA2(acc[3][0],a,w01); FMA2(acc[3][1],a,w23);
        }
        #pragma unroll
        for (int jj = 0; jj < 4; jj++) {
            float2 p0 = unpack2(acc[jj][0]), p1 = unpack2(acc[jj][1]);
            hidT[(tx*4+0)*PADJ + ty*4+jj] = silu_f(p0.x);
            hidT[(tx*4+1)*PADJ + ty*4+jj] = silu_f(p0.y);
            hidT[(tx*4+2)*PADJ + ty*4+jj] = silu_f(p1.x);
            hidT[(tx*4+3)*PADJ + ty*4+jj] = silu_f(p1.y);
        }
        __syncthreads();

        // ---- layer 2 ----
        float eb[4][4];
        {
            u64 acc2[4][2];
            float4 bv = *(const float4*)&b2[tx*4];
            #pragma unroll
            for (int jj = 0; jj < 4; jj++) {
                acc2[jj][0] = pack2(bv.x, bv.y);
                acc2[jj][1] = pack2(bv.z, bv.w);
            }
            #pragma unroll 4
            for (int kf = 0; kf < 64; kf++) {
                float4 wv = *(const float4*)&w2[kf*HH + tx*4];
                float4 av = *(float4*)&hidT[kf*PADJ + ty*4];
                u64 w01 = pack2(wv.x, wv.y), w23 = pack2(wv.z, wv.w);
                u64 a;
                a = pack2(av.x, av.x); FMA2(acc2[0][0],a,w01); FMA2(acc2[0][1],a,w23);
                a = pack2(av.y, av.y); FMA2(acc2[1][0],a,w01); FMA2(acc2[1][1],a,w23);
                a = pack2(av.z, av.z); FMA2(acc2[2][0],a,w01); FMA2(acc2[2][1],a,w23);
                a = pack2(av.w, av.w); FMA2(acc2[3][0],a,w01); FMA2(acc2[3][1],a,w23);
            }
            #pragma unroll
            for (int jj = 0; jj < 4; jj++) {
                float2 p0 = unpack2(acc2[jj][0]), p1 = unpack2(acc2[jj][1]);
                eb[jj][0] = silu_f(p0.x); eb[jj][1] = silu_f(p0.y);
                eb[jj][2] = silu_f(p1.x); eb[jj][3] = silu_f(p1.y);
            }
        }
        // store e TRANSPOSED: g_eT[bi][h][j], float4 along j
        #pragma unroll
        for (int kk = 0; kk < 4; kk++) {
            float4 ev = make_float4(eb[0][kk], eb[1][kk], eb[2][kk], eb[3][kk]);
            *(float4*)&g_eT[(bi*HH + tx*4+kk)*NN + j0 + ty*4] = ev;
        }

        // ---- sem logits ----
        float* sempart = hjT;
        #pragma unroll
        for (int jj = 0; jj < 4; jj++) {
            float p0=0.f, p1=0.f, p2=0.f, p3=0.f;
            #pragma unroll
            for (int kk = 0; kk < 4; kk++) {
                float e = eb[jj][kk];
                const float* swr = &ssw[(tx*4+kk)*4];
                p0 += e*swr[0]; p1 += e*swr[1]; p2 += e*swr[2]; p3 += e*swr[3];
            }
            float* dst = &sempart[(tx*64 + ty*4+jj)*4];
            dst[0]=p0; dst[1]=p1; dst[2]=p2; dst[3]=p3;
        }
        __syncthreads();
        {
            int jl = t >> 2, hd = t & 3;
            float a = ssb[hd];
            #pragma unroll
            for (int r = 0; r < 16; r++) a += sempart[(r*64 + jl)*4 + hd];
            a = (a > 0.f) ? a : 0.2f*a;
            g_sem[(bi*NN + j0 + jl)*HEADS + hd] = a;
        }
    }
}

// ---------------- reductions -------------------------------------------------
__device__ __forceinline__ float warpmaxf(float v){
    #pragma unroll
    for (int s=16;s;s>>=1) v = fmaxf(v, __shfl_xor_sync(0xffffffffu, v, s));
    return v;
}
__device__ __forceinline__ float warpsumf(float v){
    #pragma unroll
    for (int s=16;s;s>>=1) v += __shfl_xor_sync(0xffffffffu, v, s);
    return v;
}
__device__ __forceinline__ float4 blk_reduce4(float4 v, bool is_max, float4* redbuf){
    if (is_max) { v.x=warpmaxf(v.x); v.y=warpmaxf(v.y); v.z=warpmaxf(v.z); v.w=warpmaxf(v.w); }
    else        { v.x=warpsumf(v.x); v.y=warpsumf(v.y); v.z=warpsumf(v.z); v.w=warpsumf(v.w); }
    int w = threadIdx.x>>5, l = threadIdx.x&31;
    if (l == 0) redbuf[w] = v;
    __syncthreads();
    float4 r = redbuf[0];
    #pragma unroll
    for (int q = 1; q < 8; q++) {
        float4 o = redbuf[q];
        if (is_max) { r.x=fmaxf(r.x,o.x); r.y=fmaxf(r.y,o.y); r.z=fmaxf(r.z,o.z); r.w=fmaxf(r.w,o.w); }
        else        { r.x+=o.x; r.y+=o.y; r.z+=o.z; r.w+=o.w; }
    }
    __syncthreads();
    return r;
}
__device__ __forceinline__ float blk_sum256(float v, float* red) {
    int t = threadIdx.x;
    red[t] = v; __syncthreads();
    for (int s = 128; s > 0; s >>= 1) {
        if (t < s) red[t] += red[t + s];
        __syncthreads();
    }
    float r = red[0]; __syncthreads();
    return r;
}

// ---------------- kernel B: fused attention + aggregation -------------------
__global__ __launch_bounds__(256) void attagg_kernel(
        const float* __restrict__ x, const float* __restrict__ vmix,
        const float* __restrict__ log_gamma)
{
    __shared__ float sh_eT[64][132];     // [h][j-chunk]
    __shared__ float sattT[4][260];      // [head][j]
    __shared__ float uT[3][260];         // [dim][j]
    __shared__ float4 redbuf4[8];

    int bi = blockIdx.x;
    int b = bi >> 8, i = bi & 255;
    int t = threadIdx.x;

    // ---- phase A: attention (thread = j) ----
    {
        float4 lg = *(const float4*)log_gamma;
        float4 gm = make_float4(__expf(lg.x), __expf(lg.y), __expf(lg.z), __expf(lg.w));
        float xn = g_xnorm[bi*NN + t];
        float diag = (t == i) ? INFV : 0.f;
        float xm = xn + diag;

        float4 l1 = make_float4(-xm*gm.x, -xm*gm.y, -xm*gm.z, -xm*gm.w);
        float4 m1 = blk_reduce4(l1, true, redbuf4);
        float4 e1 = make_float4(__expf(l1.x-m1.x), __expf(l1.y-m1.y), __expf(l1.z-m1.z), __expf(l1.w-m1.w));
        float4 s1 = blk_reduce4(e1, false, redbuf4);
        float4 eu = make_float4(__fdividef(e1.x,s1.x), __fdividef(e1.y,s1.y),
                                __fdividef(e1.z,s1.z), __fdividef(e1.w,s1.w));
        float4 sl = *(const float4*)&g_sem[(bi*NN + t)*HEADS];
        sl.x -= diag; sl.y -= diag; sl.z -= diag; sl.w -= diag;
        float4 m2 = blk_reduce4(sl, true, redbuf4);
        float4 e2 = make_float4(__expf(sl.x-m2.x), __expf(sl.y-m2.y), __expf(sl.z-m2.z), __expf(sl.w-m2.w));
        float4 s2 = blk_reduce4(e2, false, redbuf4);
        float4 se = make_float4(__fdividef(e2.x,s2.x), __fdividef(e2.y,s2.y),
                                __fdividef(e2.z,s2.z), __fdividef(e2.w,s2.w));
        float4 p = make_float4(eu.x*se.x, eu.y*se.y, eu.z*se.z, eu.w*se.w);
        float4 m3 = blk_reduce4(p, true, redbuf4);
        float4 e3 = make_float4(__expf(p.x-m3.x), __expf(p.y-m3.y), __expf(p.z-m3.z), __expf(p.w-m3.w));
        float4 s3 = blk_reduce4(e3, false, redbuf4);
        sattT[0][t] = __fdividef(e3.x,s3.x);
        sattT[1][t] = __fdividef(e3.y,s3.y);
        sattT[2][t] = __fdividef(e3.z,s3.z);
        sattT[3][t] = __fdividef(e3.w,s3.w);

        float inv = __fdividef(1.f, xn + EPSV);
        uT[0][t] = (x[(b*NN+t)*3+0] - x[(b*NN+i)*3+0]) * inv;
        uT[1][t] = (x[(b*NN+t)*3+1] - x[(b*NN+i)*3+1]) * inv;
        uT[2][t] = (x[(b*NN+t)*3+2] - x[(b*NN+i)*3+2]) * inv;
    }
    __syncthreads();

    // ---- phase B: aggregation (thread = c) ----
    int c = t, hh = c >> 2, hd = c & 3;
    float agg = 0.f, cs0 = 0.f, cs1 = 0.f, cs2 = 0.f;

    for (int ch = 0; ch < 2; ch++) {
        const float* src = &g_eT[bi*HH*NN + ch*128];
        for (int idx = t; idx < 64*32; idx += 256) {
            int hr = idx >> 5, c4 = idx & 31;
            *(float4*)&sh_eT[hr][c4*4] = *(const float4*)&src[hr*NN + c4*4];
        }
        __syncthreads();
        #pragma unroll 4
        for (int q = 0; q < 32; q++) {
            float4 e4 = *(float4*)&sh_eT[hh][q*4];
            float4 a4 = *(float4*)&sattT[hd][ch*128 + q*4];
            float4 u0 = *(float4*)&uT[0][ch*128 + q*4];
            float4 u1 = *(float4*)&uT[1][ch*128 + q*4];
            float4 u2 = *(float4*)&uT[2][ch*128 + q*4];
            float w0 = e4.x*a4.x, w1 = e4.y*a4.y, w2 = e4.z*a4.z, w3 = e4.w*a4.w;
            agg += (w0 + w1) + (w2 + w3);
            cs0 += w0*u0.x + w1*u0.y + w2*u0.z + w3*u0.w;
            cs1 += w0*u1.x + w1*u1.y + w2*u1.z + w3*u1.w;
            cs2 += w0*u2.x + w1*u2.y + w2*u2.z + w3*u2.w;
        }
        __syncthreads();
    }

    const float inv_n = 1.f / (float)NN;
    cs0 *= inv_n; cs1 *= inv_n; cs2 *= inv_n;

    g_hagg[bi*CC + c]     = agg;
    g_combnorm[bi*CC + c] = cs0*cs0 + cs1*cs1 + cs2*cs2;

    float* red = (float*)sh_eT;   // safe: past last chunk sync
    float vm = vmix[c];
    float d0 = blk_sum256(vm * cs0, red);
    float d1 = blk_sum256(vm * cs1, red);
    float d2 = blk_sum256(vm * cs2, red);
    if (c == 0) {
        g_deltav[bi*3 + 0] = d0;
        g_deltav[bi*3 + 1] = d1;
        g_deltav[bi*3 + 2] = d2;
    }
}

// ---------------- kernel C: node MLPs, 4 nodes per block --------------------
// grid: BB*NN/4 = 128, block: 256. GEMM phases: thread=(k,r=K-chunk), 4 node
// accumulators per thread. Reduce phases: thread=(node=t>>6, k).
__global__ __launch_bounds__(256) void node_kernel(
        const float* __restrict__ h, const float* __restrict__ x,
        const float* __restrict__ v,
        const float* __restrict__ pw1, const float* __restrict__ pb1,
        const float* __restrict__ pw2, const float* __restrict__ pb2,
        const float* __restrict__ nw1, const float* __restrict__ nb1,
        const float* __restrict__ nw2, const float* __restrict__ nb2,
        const float* __restrict__ vw1, const float* __restrict__ vb1,
        const float* __restrict__ vw2,
        float* __restrict__ out)
{
    __shared__ float cnT[256*4];      // [u][node]
    __shared__ float nactT[384*4];    // [h(64) | hagg(256) | hcomb(64)][node]
    __shared__ float hidT[64*4];
    __shared__ float hnewT[64*4];
    __shared__ float sbuf[16*64];     // [r][node][k]
    __shared__ float wbuf[8];
    __shared__ float vsc[4];

    int bi = blockIdx.x;
    int t = threadIdx.x;
    int k = t & 63, r = t >> 6;
    int node = r;

    #pragma unroll
    for (int q = 0; q < 4; q++) {
        int u = k + q*64;
        cnT[u*4 + node]        = g_combnorm[(bi*4 + node)*CC + u];
        nactT[(64+u)*4 + node] = g_hagg[(bi*4 + node)*CC + u];
    }
    nactT[k*4 + node] = h[(bi*4 + node)*FF + k];
    __syncthreads();

    // ---- post1: K=256, act=cnT, out=hidT ----
    {
        float a0=0,a1=0,a2=0,a3=0;
        #pragma unroll 4
        for (int uu = 0; uu < 64; uu++) {
            int u = r*64 + uu;
            float w = __ldg(&pw1[u*HH + k]);
            float4 a4 = *(float4*)&cnT[u*4];
            a0 += a4.x*w; a1 += a4.y*w; a2 += a4.z*w; a3 += a4.w*w;
        }
        sbuf[(r*4+0)*64+k]=a0; sbuf[(r*4+1)*64+k]=a1;
        sbuf[(r*4+2)*64+k]=a2; sbuf[(r*4+3)*64+k]=a3;
    }
    __syncthreads();
    hidT[k*4+node] = silu_f(sbuf[(0*4+node)*64+k] + sbuf[(1*4+node)*64+k]
                          + sbuf[(2*4+node)*64+k] + sbuf[(3*4+node)*64+k] + pb1[k]);
    __syncthreads();

    // ---- post2: K=64, act=hidT, out=nactT[320..] ----
    {
        float a0=0,a1=0,a2=0,a3=0;
        #pragma unroll
        for (int uu = 0; uu < 16; uu++) {
            int u = r*16 + uu;
            float w = __ldg(&pw2[u*HH + k]);
            float4 a4 = *(float4*)&hidT[u*4];
            a0 += a4.x*w; a1 += a4.y*w; a2 += a4.z*w; a3 += a4.w*w;
        }
        sbuf[(r*4+0)*64+k]=a0; sbuf[(r*4+1)*64+k]=a1;
        sbuf[(r*4+2)*64+k]=a2; sbuf[(r*4+3)*64+k]=a3;
    }
    __syncthreads();
    nactT[(320+k)*4+node] = silu_f(sbuf[(0*4+node)*64+k] + sbuf[(1*4+node)*64+k]
                                 + sbuf[(2*4+node)*64+k] + sbuf[(3*4+node)*64+k] + pb2[k]);
    __syncthreads();

    // ---- node1: K=384, act=nactT, out=hidT ----
    {
        float a0=0,a1=0,a2=0,a3=0;
        #pragma unroll 4
        for (int uu = 0; uu < 96; uu++) {
            int u = r*96 + uu;
            float w = __ldg(&nw1[u*HH + k]);
            float4 a4 = *(float4*)&nactT[u*4];
            a0 += a4.x*w; a1 += a4.y*w; a2 += a4.z*w; a3 += a4.w*w;
        }
        sbuf[(r*4+0)*64+k]=a0; sbuf[(r*4+1)*64+k]=a1;
        sbuf[(r*4+2)*64+k]=a2; sbuf[(r*4+3)*64+k]=a3;
    }
    __syncthreads();
    hidT[k*4+node] = silu_f(sbuf[(0*4+node)*64+k] + sbuf[(1*4+node)*64+k]
                          + sbuf[(2*4+node)*64+k] + sbuf[(3*4+node)*64+k] + nb1[k]);
    __syncthreads();

    // ---- node2: K=64, act=hidT, residual, write h_new ----
    {
        float a0=0,a1=0,a2=0,a3=0;
        #pragma unroll
        for (int uu = 0; uu < 16; uu++) {
            int u = r*16 + uu;
            float w = __ldg(&nw2[u*HH + k]);
            float4 a4 = *(float4*)&hidT[u*4];
            a0 += a4.x*w; a1 += a4.y*w; a2 += a4.z*w; a3 += a4.w*w;
        }
        sbuf[(r*4+0)*64+k]=a0; sbuf[(r*4+1)*64+k]=a1;
        sbuf[(r*4+2)*64+k]=a2; sbuf[(r*4+3)*64+k]=a3;
    }
    __syncthreads();
    {
        float hn = nactT[k*4+node] + silu_f(sbuf[(0*4+node)*64+k] + sbuf[(1*4+node)*64+k]
                                          + sbuf[(2*4+node)*64+k] + sbuf[(3*4+node)*64+k] + nb2[k]);
        hnewT[k*4+node] = hn;
        out[(bi*4+node)*FF + k] = hn;
    }
    __syncthreads();

    // ---- vel: K=64, act=hnewT, scalar per node ----
    {
        float a0=0,a1=0,a2=0,a3=0;
        #pragma unroll
        for (int uu = 0; uu < 16; uu++) {
            int u = r*16 + uu;
            float w = __ldg(&vw1[u*HH + k]);
            float4 a4 = *(float4*)&hnewT[u*4];
            a0 += a4.x*w; a1 += a4.y*w; a2 += a4.z*w; a3 += a4.w*w;
        }
        sbuf[(r*4+0)*64+k]=a0; sbuf[(r*4+1)*64+k]=a1;
        sbuf[(r*4+2)*64+k]=a2; sbuf[(r*4+3)*64+k]=a3;
    }
    __syncthreads();
    {
        float s = sbuf[(0*4+node)*64+k] + sbuf[(1*4+node)*64+k]
                + sbuf[(2*4+node)*64+k] + sbuf[(3*4+node)*64+k];
        float sv = silu_f(s + vb1[k]) * __ldg(&vw2[k]);
        sv = warpsumf(sv);
        if ((t & 31) == 0) wbuf[t >> 5] = sv;
    }
    __syncthreads();
    if (t < 4) vsc[t] = wbuf[t*2] + wbuf[t*2+1];
    __syncthreads();
    if (t < 12) {
        int nd = t / 3, d = t % 3;
        int gi = bi*4 + nd;
        float vv = v[gi*3 + d];
        float vn = g_deltav[gi*3 + d] + vsc[nd]*vv;
        out[BB*NN*FF + gi*3 + d]            = x[gi*3 + d] + vn;  // x_new
        out[BB*NN*FF + BB*NN*3 + gi*3 + d]  = vn;                // v_new
    }
}

// ---------------------------------------------------------------------------
extern "C" void kernel_launch(void* const* d_in, const int* in_sizes, int n_in,
                              void* d_out, int out_size)
{
    const float* h        = (const float*)d_in[0];
    const float* x        = (const float*)d_in[1];
    const float* v        = (const float*)d_in[2];
    const float* edge_w1  = (const float*)d_in[3];
    const float* edge_b1  = (const float*)d_in[4];
    const float* edge_w2  = (const float*)d_in[5];
    const float* edge_b2  = (const float*)d_in[6];
    const float* sem_w    = (const float*)d_in[7];
    const float* sem_b    = (const float*)d_in[8];
    const float* post_w1  = (const float*)d_in[9];
    const float* post_b1  = (const float*)d_in[10];
    const float* post_w2  = (const float*)d_in[11];
    const float* post_b2  = (const float*)d_in[12];
    const float* node_w1  = (const float*)d_in[13];
    const float* node_b1  = (const float*)d_in[14];
    const float* node_w2  = (const float*)d_in[15];
    const float* node_b2  = (const float*)d_in[16];
    const float* vel_w1   = (const float*)d_in[17];
    const float* vel_b1   = (const float*)d_in[18];
    const float* vel_w2   = (const float*)d_in[19];
    const float* vmix_w   = (const float*)d_in[20];
    const float* log_gamma= (const float*)d_in[21];
    float* out = (float*)d_out;

    edge_kernel<<<BB*NN, 256>>>(h, x, edge_w1, edge_b1, edge_w2, edge_b2, sem_w, sem_b);
    attagg_kernel<<<BB*NN, 256>>>(x, vmix_w, log_gamma);
    node_kernel<<<BB*NN/4, 256>>>(h, x, v,
                                  post_w1, post_b1, post_w2, post_b2,
                                  node_w1, node_b1, node_w2, node_b2,
                                  vel_w1, vel_b1, vel_w2, out);
}

// round 5
// speedup vs baseline: 3.5977x; 1.3651x over previous
#include <cuda_runtime.h>
#include <math.h>

#define BB 2
#define NN 256
#define FF 64
#define HH 64
#define HEADS 4
#define CC 256
#define EPSV 1e-5f
#define INFV 1e5f
#define PADJ 68

typedef unsigned long long u64;

// ---------------- scratch (device globals) ----------------------------------
__device__ float g_eT[BB*NN*HH*NN];         // [bi][h][j]
__device__ float g_sem[BB*NN*NN*HEADS];
__device__ float g_AT[BB*HH*NN];            // A[b][k][j] = h_j @ W1[0:64]
__device__ float g_acci[BB*NN*HH];          // acci[bi][k] = b1 + h_i @ W1[64:128]
__device__ float g_combnorm[BB*NN*CC];
__device__ float g_hagg[BB*NN*CC];
__device__ float g_deltav[BB*NN*3];

__device__ __forceinline__ float silu_f(float v){ return __fdividef(v, 1.f + __expf(-v)); }

__device__ __forceinline__ u64 pack2(float lo, float hi){
    u64 r; unsigned lu = __float_as_uint(lo), hu = __float_as_uint(hi);
    asm("mov.b64 %0, {%1, %2};" : "=l"(r) : "r"(lu), "r"(hu));
    return r;
}
__device__ __forceinline__ float2 unpack2(u64 v){
    unsigned lu, hu;
    asm("mov.b64 {%0, %1}, %2;" : "=r"(lu), "=r"(hu) : "l"(v));
    return make_float2(__uint_as_float(lu), __uint_as_float(hu));
}
#define FMA2(acc,a,b) asm("fma.rn.f32x2 %0, %1, %2, %3;" : "=l"(acc) : "l"(a), "l"(b), "l"(acc))

// ---------------- kernel P: precompute A and acci ----------------------------
// grid: BB*NN = 512, block: 128 (t<64: A row, t>=64: acci row)
__global__ __launch_bounds__(128) void pre_kernel(
        const float* __restrict__ h, const float* __restrict__ w1,
        const float* __restrict__ b1)
{
    int bi = blockIdx.x;
    int b = bi >> 8, j = bi & 255;
    __shared__ float sh[64];
    int t = threadIdx.x;
    if (t < 64) sh[t] = h[bi*FF + t];
    __syncthreads();
    int k = t & 63;
    const float* wbase = (t < 64) ? w1 : (w1 + 64*HH);
    float a0=0,a1=0,a2=0,a3=0;
    #pragma unroll 8
    for (int f = 0; f < 64; f += 4) {
        a0 += sh[f+0]*__ldg(&wbase[(f+0)*HH + k]);
        a1 += sh[f+1]*__ldg(&wbase[(f+1)*HH + k]);
        a2 += sh[f+2]*__ldg(&wbase[(f+2)*HH + k]);
        a3 += sh[f+3]*__ldg(&wbase[(f+3)*HH + k]);
    }
    float a = (a0+a1)+(a2+a3);
    if (t < 64) g_AT[(b*HH + k)*NN + j] = a;
    else        g_acci[bi*HH + k] = a + b1[k];
}

// ---------------- kernel A: edge layer2 + sem, layer1 via precomputed A -----
// grid: BB*NN*2 = 1024 (bi, half), block: 256
__global__ __launch_bounds__(256) void edge_kernel(
        const float* __restrict__ x,
        const float* __restrict__ w1,
        const float* __restrict__ w2, const float* __restrict__ b2,
        const float* __restrict__ sw, const float* __restrict__ sb)
{
    int blk = blockIdx.x;
    int bi = blk >> 1, half = blk & 1;
    int b = bi >> 8, i = bi & 255;
    int t = threadIdx.x;
    int tx = t & 15, ty = t >> 4;

    __shared__ float hidT[64*PADJ];   // [k][j]; reused as sem partials
    __shared__ float acci_s[64];
    __shared__ float w1x_s[64];
    __shared__ float xnorm_s[128];
    __shared__ float ssw[256];
    __shared__ float ssb[4];

    if (t < 64) { acci_s[t] = g_acci[bi*HH + t]; w1x_s[t] = w1[128*HH + t]; }
    ssw[t] = sw[t];
    if (t < 4) ssb[t] = sb[t];
    if (t < 128) {
        int j = half*128 + t;
        float dx = x[(b*NN + j)*3+0] - x[(b*NN + i)*3+0];
        float dy = x[(b*NN + j)*3+1] - x[(b*NN + i)*3+1];
        float dz = x[(b*NN + j)*3+2] - x[(b*NN + i)*3+2];
        xnorm_s[t] = sqrtf(dx*dx + dy*dy + dz*dz + EPSV);
    }

    for (int jt = 0; jt < 2; jt++) {
        int j0g = half*128 + jt*64;   // global j base
        int xb  = jt*64;              // xnorm_s base
        __syncthreads();

        // ---- layer-1 elementwise from precomputed A/acci ----
        {
            int k = t >> 2, jg = t & 3;
            float ac = acci_s[k], wx = w1x_s[k];
            const float* Arow = &g_AT[(b*HH + k)*NN + j0g];
            #pragma unroll
            for (int q = 0; q < 4; q++) {
                int jl = jg*16 + q*4;
                float4 av = *(const float4*)&Arow[jl];
                float4 xv = *(const float4*)&xnorm_s[xb + jl];
                float4 hv;
                hv.x = silu_f(fmaf(xv.x, wx, av.x + ac));
                hv.y = silu_f(fmaf(xv.y, wx, av.y + ac));
                hv.z = silu_f(fmaf(xv.z, wx, av.z + ac));
                hv.w = silu_f(fmaf(xv.w, wx, av.w + ac));
                *(float4*)&hidT[k*PADJ + jl] = hv;
            }
        }
        __syncthreads();

        // ---- layer 2 GEMM (4j x 4k per thread) ----
        float eb[4][4];
        {
            u64 acc2[4][2];
            float4 bv = *(const float4*)&b2[tx*4];
            #pragma unroll
            for (int jj = 0; jj < 4; jj++) {
                acc2[jj][0] = pack2(bv.x, bv.y);
                acc2[jj][1] = pack2(bv.z, bv.w);
            }
            #pragma unroll 4
            for (int kf = 0; kf < 64; kf++) {
                float4 wv = *(const float4*)&w2[kf*HH + tx*4];
                float4 av = *(float4*)&hidT[kf*PADJ + ty*4];
                u64 w01 = pack2(wv.x, wv.y), w23 = pack2(wv.z, wv.w);
                u64 a;
                a = pack2(av.x, av.x); FMA2(acc2[0][0],a,w01); FMA2(acc2[0][1],a,w23);
                a = pack2(av.y, av.y); FMA2(acc2[1][0],a,w01); FMA2(acc2[1][1],a,w23);
                a = pack2(av.z, av.z); FMA2(acc2[2][0],a,w01); FMA2(acc2[2][1],a,w23);
                a = pack2(av.w, av.w); FMA2(acc2[3][0],a,w01); FMA2(acc2[3][1],a,w23);
            }
            #pragma unroll
            for (int jj = 0; jj < 4; jj++) {
                float2 p0 = unpack2(acc2[jj][0]), p1 = unpack2(acc2[jj][1]);
                eb[jj][0] = silu_f(p0.x); eb[jj][1] = silu_f(p0.y);
                eb[jj][2] = silu_f(p1.x); eb[jj][3] = silu_f(p1.y);
            }
        }
        // store e TRANSPOSED: g_eT[bi][h][j]
        #pragma unroll
        for (int kk = 0; kk < 4; kk++) {
            float4 ev = make_float4(eb[0][kk], eb[1][kk], eb[2][kk], eb[3][kk]);
            *(float4*)&g_eT[(bi*HH + tx*4+kk)*NN + j0g + ty*4] = ev;
        }
        __syncthreads();   // all GEMM reads of hidT done before aliasing

        // ---- sem logits: partials into hidT (aliased), reduce ----
        float* sempart = hidT;
        #pragma unroll
        for (int jj = 0; jj < 4; jj++) {
            float p0=0.f, p1=0.f, p2=0.f, p3=0.f;
            #pragma unroll
            for (int kk = 0; kk < 4; kk++) {
                float e = eb[jj][kk];
                const float* swr = &ssw[(tx*4+kk)*4];
                p0 += e*swr[0]; p1 += e*swr[1]; p2 += e*swr[2]; p3 += e*swr[3];
            }
            float* dst = &sempart[(tx*64 + ty*4+jj)*4];
            dst[0]=p0; dst[1]=p1; dst[2]=p2; dst[3]=p3;
        }
        __syncthreads();
        {
            int jl = t >> 2, hd = t & 3;
            float a = ssb[hd];
            #pragma unroll
            for (int r = 0; r < 16; r++) a += sempart[(r*64 + jl)*4 + hd];
            a = (a > 0.f) ? a : 0.2f*a;
            g_sem[(bi*NN + j0g + jl)*HEADS + hd] = a;
        }
    }
}

// ---------------- reductions -------------------------------------------------
__device__ __forceinline__ float warpmaxf(float v){
    #pragma unroll
    for (int s=16;s;s>>=1) v = fmaxf(v, __shfl_xor_sync(0xffffffffu, v, s));
    return v;
}
__device__ __forceinline__ float warpsumf(float v){
    #pragma unroll
    for (int s=16;s;s>>=1) v += __shfl_xor_sync(0xffffffffu, v, s);
    return v;
}
__device__ __forceinline__ float4 blk_reduce4(float4 v, bool is_max, float4* redbuf){
    if (is_max) { v.x=warpmaxf(v.x); v.y=warpmaxf(v.y); v.z=warpmaxf(v.z); v.w=warpmaxf(v.w); }
    else        { v.x=warpsumf(v.x); v.y=warpsumf(v.y); v.z=warpsumf(v.z); v.w=warpsumf(v.w); }
    int w = threadIdx.x>>5, l = threadIdx.x&31;
    if (l == 0) redbuf[w] = v;
    __syncthreads();
    float4 r = redbuf[0];
    #pragma unroll
    for (int q = 1; q < 8; q++) {
        float4 o = redbuf[q];
        if (is_max) { r.x=fmaxf(r.x,o.x); r.y=fmaxf(r.y,o.y); r.z=fmaxf(r.z,o.z); r.w=fmaxf(r.w,o.w); }
        else        { r.x+=o.x; r.y+=o.y; r.z+=o.z; r.w+=o.w; }
    }
    __syncthreads();
    return r;
}
__device__ __forceinline__ float blk_sum256(float v, float* red) {
    int t = threadIdx.x;
    red[t] = v; __syncthreads();
    for (int s = 128; s > 0; s >>= 1) {
        if (t < s) red[t] += red[t + s];
        __syncthreads();
    }
    float r = red[0]; __syncthreads();
    return r;
}

// ---------------- kernel B: fused attention + aggregation -------------------
__global__ __launch_bounds__(256) void attagg_kernel(
        const float* __restrict__ x, const float* __restrict__ vmix,
        const float* __restrict__ log_gamma)
{
    __shared__ float sh_eT[64][132];     // [h][j-chunk]
    __shared__ float sattT[4][260];      // [head][j]
    __shared__ float uT[3][260];         // [dim][j]
    __shared__ float4 redbuf4[8];

    int bi = blockIdx.x;
    int b = bi >> 8, i = bi & 255;
    int t = threadIdx.x;

    // ---- phase A: attention (thread = j) ----
    {
        float4 lg = *(const float4*)log_gamma;
        float4 gm = make_float4(__expf(lg.x), __expf(lg.y), __expf(lg.z), __expf(lg.w));
        float dx = x[(b*NN+t)*3+0] - x[(b*NN+i)*3+0];
        float dy = x[(b*NN+t)*3+1] - x[(b*NN+i)*3+1];
        float dz = x[(b*NN+t)*3+2] - x[(b*NN+i)*3+2];
        float xn = sqrtf(dx*dx + dy*dy + dz*dz + EPSV);
        float diag = (t == i) ? INFV : 0.f;
        float xm = xn + diag;

        float4 l1 = make_float4(-xm*gm.x, -xm*gm.y, -xm*gm.z, -xm*gm.w);
        float4 m1 = blk_reduce4(l1, true, redbuf4);
        float4 e1 = make_float4(__expf(l1.x-m1.x), __expf(l1.y-m1.y), __expf(l1.z-m1.z), __expf(l1.w-m1.w));
        float4 s1 = blk_reduce4(e1, false, redbuf4);
        float4 eu = make_float4(__fdividef(e1.x,s1.x), __fdividef(e1.y,s1.y),
                                __fdividef(e1.z,s1.z), __fdividef(e1.w,s1.w));
        float4 sl = *(const float4*)&g_sem[(bi*NN + t)*HEADS];
        sl.x -= diag; sl.y -= diag; sl.z -= diag; sl.w -= diag;
        float4 m2 = blk_reduce4(sl, true, redbuf4);
        float4 e2 = make_float4(__expf(sl.x-m2.x), __expf(sl.y-m2.y), __expf(sl.z-m2.z), __expf(sl.w-m2.w));
        float4 s2 = blk_reduce4(e2, false, redbuf4);
        float4 se = make_float4(__fdividef(e2.x,s2.x), __fdividef(e2.y,s2.y),
                                __fdividef(e2.z,s2.z), __fdividef(e2.w,s2.w));
        float4 p = make_float4(eu.x*se.x, eu.y*se.y, eu.z*se.z, eu.w*se.w);
        float4 m3 = blk_reduce4(p, true, redbuf4);
        float4 e3 = make_float4(__expf(p.x-m3.x), __expf(p.y-m3.y), __expf(p.z-m3.z), __expf(p.w-m3.w));
        float4 s3 = blk_reduce4(e3, false, redbuf4);
        sattT[0][t] = __fdividef(e3.x,s3.x);
        sattT[1][t] = __fdividef(e3.y,s3.y);
        sattT[2][t] = __fdividef(e3.z,s3.z);
        sattT[3][t] = __fdividef(e3.w,s3.w);

        float inv = __fdividef(1.f, xn + EPSV);
        uT[0][t] = dx * inv;
        uT[1][t] = dy * inv;
        uT[2][t] = dz * inv;
    }
    __syncthreads();

    // ---- phase B: aggregation (thread = c) ----
    int c = t, hh = c >> 2, hd = c & 3;
    float agg = 0.f, cs0 = 0.f, cs1 = 0.f, cs2 = 0.f;

    for (int ch = 0; ch < 2; ch++) {
        const float* src = &g_eT[bi*HH*NN + ch*128];
        for (int idx = t; idx < 64*32; idx += 256) {
            int hr = idx >> 5, c4 = idx & 31;
            *(float4*)&sh_eT[hr][c4*4] = *(const float4*)&src[hr*NN + c4*4];
        }
        __syncthreads();
        #pragma unroll 4
        for (int q = 0; q < 32; q++) {
            float4 e4 = *(float4*)&sh_eT[hh][q*4];
            float4 a4 = *(float4*)&sattT[hd][ch*128 + q*4];
            float4 u0 = *(float4*)&uT[0][ch*128 + q*4];
            float4 u1 = *(float4*)&uT[1][ch*128 + q*4];
            float4 u2 = *(float4*)&uT[2][ch*128 + q*4];
            float w0 = e4.x*a4.x, w1 = e4.y*a4.y, w2 = e4.z*a4.z, w3 = e4.w*a4.w;
            agg += (w0 + w1) + (w2 + w3);
            cs0 += w0*u0.x + w1*u0.y + w2*u0.z + w3*u0.w;
            cs1 += w0*u1.x + w1*u1.y + w2*u1.z + w3*u1.w;
            cs2 += w0*u2.x + w1*u2.y + w2*u2.z + w3*u2.w;
        }
        __syncthreads();
    }

    const float inv_n = 1.f / (float)NN;
    cs0 *= inv_n; cs1 *= inv_n; cs2 *= inv_n;

    g_hagg[bi*CC + c]     = agg;
    g_combnorm[bi*CC + c] = cs0*cs0 + cs1*cs1 + cs2*cs2;

    float* red = (float*)sh_eT;
    float vm = vmix[c];
    float d0 = blk_sum256(vm * cs0, red);
    float d1 = blk_sum256(vm * cs1, red);
    float d2 = blk_sum256(vm * cs2, red);
    if (c == 0) {
        g_deltav[bi*3 + 0] = d0;
        g_deltav[bi*3 + 1] = d1;
        g_deltav[bi*3 + 2] = d2;
    }
}

// ---------------- kernel C: node MLPs, 4 nodes per block --------------------
__global__ __launch_bounds__(256) void node_kernel(
        const float* __restrict__ h, const float* __restrict__ x,
        const float* __restrict__ v,
        const float* __restrict__ pw1, const float* __restrict__ pb1,
        const float* __restrict__ pw2, const float* __restrict__ pb2,
        const float* __restrict__ nw1, const float* __restrict__ nb1,
        const float* __restrict__ nw2, const float* __restrict__ nb2,
        const float* __restrict__ vw1, const float* __restrict__ vb1,
        const float* __restrict__ vw2,
        float* __restrict__ out)
{
    __shared__ float cnT[256*4];
    __shared__ float nactT[384*4];
    __shared__ float hidT[64*4];
    __shared__ float hnewT[64*4];
    __shared__ float sbuf[16*64];
    __shared__ float wbuf[8];
    __shared__ float vsc[4];

    int bi = blockIdx.x;
    int t = threadIdx.x;
    int k = t & 63, r = t >> 6;
    int node = r;

    #pragma unroll
    for (int q = 0; q < 4; q++) {
        int u = k + q*64;
        cnT[u*4 + node]        = g_combnorm[(bi*4 + node)*CC + u];
        nactT[(64+u)*4 + node] = g_hagg[(bi*4 + node)*CC + u];
    }
    nactT[k*4 + node] = h[(bi*4 + node)*FF + k];
    __syncthreads();

    // post1
    {
        float a0=0,a1=0,a2=0,a3=0;
        #pragma unroll 4
        for (int uu = 0; uu < 64; uu++) {
            int u = r*64 + uu;
            float w = __ldg(&pw1[u*HH + k]);
            float4 a4 = *(float4*)&cnT[u*4];
            a0 += a4.x*w; a1 += a4.y*w; a2 += a4.z*w; a3 += a4.w*w;
        }
        sbuf[(r*4+0)*64+k]=a0; sbuf[(r*4+1)*64+k]=a1;
        sbuf[(r*4+2)*64+k]=a2; sbuf[(r*4+3)*64+k]=a3;
    }
    __syncthreads();
    hidT[k*4+node] = silu_f(sbuf[(0*4+node)*64+k] + sbuf[(1*4+node)*64+k]
                          + sbuf[(2*4+node)*64+k] + sbuf[(3*4+node)*64+k] + pb1[k]);
    __syncthreads();

    // post2
    {
        float a0=0,a1=0,a2=0,a3=0;
        #pragma unroll
        for (int uu = 0; uu < 16; uu++) {
            int u = r*16 + uu;
            float w = __ldg(&pw2[u*HH + k]);
            float4 a4 = *(float4*)&hidT[u*4];
            a0 += a4.x*w; a1 += a4.y*w; a2 += a4.z*w; a3 += a4.w*w;
        }
        sbuf[(r*4+0)*64+k]=a0; sbuf[(r*4+1)*64+k]=a1;
        sbuf[(r*4+2)*64+k]=a2; sbuf[(r*4+3)*64+k]=a3;
    }
    __syncthreads();
    nactT[(320+k)*4+node] = silu_f(sbuf[(0*4+node)*64+k] + sbuf[(1*4+node)*64+k]
                                 + sbuf[(2*4+node)*64+k] + sbuf[(3*4+node)*64+k] + pb2[k]);
    __syncthreads();

    // node1
    {
        float a0=0,a1=0,a2=0,a3=0;
        #pragma unroll 4
        for (int uu = 0; uu < 96; uu++) {
            int u = r*96 + uu;
            float w = __ldg(&nw1[u*HH + k]);
            float4 a4 = *(float4*)&nactT[u*4];
            a0 += a4.x*w; a1 += a4.y*w; a2 += a4.z*w; a3 += a4.w*w;
        }
        sbuf[(r*4+0)*64+k]=a0; sbuf[(r*4+1)*64+k]=a1;
        sbuf[(r*4+2)*64+k]=a2; sbuf[(r*4+3)*64+k]=a3;
    }
    __syncthreads();
    hidT[k*4+node] = silu_f(sbuf[(0*4+node)*64+k] + sbuf[(1*4+node)*64+k]
                          + sbuf[(2*4+node)*64+k] + sbuf[(3*4+node)*64+k] + nb1[k]);
    __syncthreads();

    // node2 + residual
    {
        float a0=0,a1=0,a2=0,a3=0;
        #pragma unroll
        for (int uu = 0; uu < 16; uu++) {
            int u = r*16 + uu;
            float w = __ldg(&nw2[u*HH + k]);
            float4 a4 = *(float4*)&hidT[u*4];
            a0 += a4.x*w; a1 += a4.y*w; a2 += a4.z*w; a3 += a4.w*w;
        }
        sbuf[(r*4+0)*64+k]=a0; sbuf[(r*4+1)*64+k]=a1;
        sbuf[(r*4+2)*64+k]=a2; sbuf[(r*4+3)*64+k]=a3;
    }
    __syncthreads();
    {
        float hn = nactT[k*4+node] + silu_f(sbuf[(0*4+node)*64+k] + sbuf[(1*4+node)*64+k]
                                          + sbuf[(2*4+node)*64+k] + sbuf[(3*4+node)*64+k] + nb2[k]);
        hnewT[k*4+node] = hn;
        out[(bi*4+node)*FF + k] = hn;
    }
    __syncthreads();

    // vel
    {
        float a0=0,a1=0,a2=0,a3=0;
        #pragma unroll
        for (int uu = 0; uu < 16; uu++) {
            int u = r*16 + uu;
            float w = __ldg(&vw1[u*HH + k]);
            float4 a4 = *(float4*)&hnewT[u*4];
            a0 += a4.x*w; a1 += a4.y*w; a2 += a4.z*w; a3 += a4.w*w;
        }
        sbuf[(r*4+0)*64+k]=a0; sbuf[(r*4+1)*64+k]=a1;
        sbuf[(r*4+2)*64+k]=a2; sbuf[(r*4+3)*64+k]=a3;
    }
    __syncthreads();
    {
        float s = sbuf[(0*4+node)*64+k] + sbuf[(1*4+node)*64+k]
                + sbuf[(2*4+node)*64+k] + sbuf[(3*4+node)*64+k];
        float sv = silu_f(s + vb1[k]) * __ldg(&vw2[k]);
        sv = warpsumf(sv);
        if ((t & 31) == 0) wbuf[t >> 5] = sv;
    }
    __syncthreads();
    if (t < 4) vsc[t] = wbuf[t*2] + wbuf[t*2+1];
    __syncthreads();
    if (t < 12) {
        int nd = t / 3, d = t % 3;
        int gi = bi*4 + nd;
        float vv = v[gi*3 + d];
        float vn = g_deltav[gi*3 + d] + vsc[nd]*vv;
        out[BB*NN*FF + gi*3 + d]            = x[gi*3 + d] + vn;
        out[BB*NN*FF + BB*NN*3 + gi*3 + d]  = vn;
    }
}

// ---------------------------------------------------------------------------
extern "C" void kernel_launch(void* const* d_in, const int* in_sizes, int n_in,
                              void* d_out, int out_size)
{
    const float* h        = (const float*)d_in[0];
    const float* x        = (const float*)d_in[1];
    const float* v        = (const float*)d_in[2];
    const float* edge_w1  = (const float*)d_in[3];
    const float* edge_b1  = (const float*)d_in[4];
    const float* edge_w2  = (const float*)d_in[5];
    const float* edge_b2  = (const float*)d_in[6];
    const float* sem_w    = (const float*)d_in[7];
    const float* sem_b    = (const float*)d_in[8];
    const float* post_w1  = (const float*)d_in[9];
    const float* post_b1  = (const float*)d_in[10];
    const float* post_w2  = (const float*)d_in[11];
    const float* post_b2  = (const float*)d_in[12];
    const float* node_w1  = (const float*)d_in[13];
    const float* node_b1  = (const float*)d_in[14];
    const float* node_w2  = (const float*)d_in[15];
    const float* node_b2  = (const float*)d_in[16];
    const float* vel_w1   = (const float*)d_in[17];
    const float* vel_b1   = (const float*)d_in[18];
    const float* vel_w2   = (const float*)d_in[19];
    const float* vmix_w   = (const float*)d_in[20];
    const float* log_gamma= (const float*)d_in[21];
    float* out = (float*)d_out;

    pre_kernel<<<BB*NN, 128>>>(h, edge_w1, edge_b1);
    edge_kernel<<<BB*NN*2, 256>>>(x, edge_w1, edge_w2, edge_b2, sem_w, sem_b);
    attagg_kernel<<<BB*NN, 256>>>(x, vmix_w, log_gamma);
    node_kernel<<<BB*NN/4, 256>>>(h, x, v,
                                  post_w1, post_b1, post_w2, post_b2,
                                  node_w1, node_b1, node_w2, node_b2,
                                  vel_w1, vel_b1, vel_w2, out);
}

// round 6
// speedup vs baseline: 4.2076x; 1.1695x over previous
#include <cuda_runtime.h>
#include <math.h>

#define BB 2
#define NN 256
#define FF 64
#define HH 64
#define HEADS 4
#define CC 256
#define EPSV 1e-5f
#define INFV 1e5f
#define PADJ 68

typedef unsigned long long u64;

// ---------------- scratch (device globals) ----------------------------------
__device__ float g_eT[BB*NN*HH*NN];         // [bi][h][j]
__device__ float g_sem[BB*NN*NN*HEADS];
__device__ float g_AT[BB*HH*NN];            // A[b][k][j] = h_j @ W1[0:64]
__device__ float g_acci[BB*NN*HH];          // acci[bi][k] = b1 + h_i @ W1[64:128]
__device__ float g_combnorm[BB*NN*CC];
__device__ float g_hagg[BB*NN*CC];
__device__ float g_deltav[BB*NN*3];

__device__ __forceinline__ float silu_f(float v){ return __fdividef(v, 1.f + __expf(-v)); }

__device__ __forceinline__ u64 pack2(float lo, float hi){
    u64 r; unsigned lu = __float_as_uint(lo), hu = __float_as_uint(hi);
    asm("mov.b64 %0, {%1, %2};" : "=l"(r) : "r"(lu), "r"(hu));
    return r;
}
__device__ __forceinline__ float2 unpack2(u64 v){
    unsigned lu, hu;
    asm("mov.b64 {%0, %1}, %2;" : "=r"(lu), "=r"(hu) : "l"(v));
    return make_float2(__uint_as_float(lu), __uint_as_float(hu));
}
#define FMA2(acc,a,b) asm("fma.rn.f32x2 %0, %1, %2, %3;" : "=l"(acc) : "l"(a), "l"(b), "l"(acc))

// ---------------- kernel P: precompute A and acci ----------------------------
__global__ __launch_bounds__(128) void pre_kernel(
        const float* __restrict__ h, const float* __restrict__ w1,
        const float* __restrict__ b1)
{
    int bi = blockIdx.x;
    int b = bi >> 8, j = bi & 255;
    __shared__ float sh[64];
    int t = threadIdx.x;
    if (t < 64) sh[t] = h[bi*FF + t];
    __syncthreads();
    int k = t & 63;
    const float* wbase = (t < 64) ? w1 : (w1 + 64*HH);
    float a0=0,a1=0,a2=0,a3=0;
    #pragma unroll 8
    for (int f = 0; f < 64; f += 4) {
        a0 += sh[f+0]*__ldg(&wbase[(f+0)*HH + k]);
        a1 += sh[f+1]*__ldg(&wbase[(f+1)*HH + k]);
        a2 += sh[f+2]*__ldg(&wbase[(f+2)*HH + k]);
        a3 += sh[f+3]*__ldg(&wbase[(f+3)*HH + k]);
    }
    float a = (a0+a1)+(a2+a3);
    if (t < 64) g_AT[(b*HH + k)*NN + j] = a;
    else        g_acci[bi*HH + k] = a + b1[k];
}

// ---------------- kernel A: edge layer2 + sem -------------------------------
__global__ __launch_bounds__(256) void edge_kernel(
        const float* __restrict__ x,
        const float* __restrict__ w1,
        const float* __restrict__ w2, const float* __restrict__ b2,
        const float* __restrict__ sw, const float* __restrict__ sb)
{
    int blk = blockIdx.x;
    int bi = blk >> 1, half = blk & 1;
    int b = bi >> 8, i = bi & 255;
    int t = threadIdx.x;
    int tx = t & 15, ty = t >> 4;

    __shared__ float hidT[64*PADJ];
    __shared__ float acci_s[64];
    __shared__ float w1x_s[64];
    __shared__ float xnorm_s[128];
    __shared__ float ssw[256];
    __shared__ float ssb[4];

    if (t < 64) { acci_s[t] = g_acci[bi*HH + t]; w1x_s[t] = w1[128*HH + t]; }
    ssw[t] = sw[t];
    if (t < 4) ssb[t] = sb[t];
    if (t < 128) {
        int j = half*128 + t;
        float dx = x[(b*NN + j)*3+0] - x[(b*NN + i)*3+0];
        float dy = x[(b*NN + j)*3+1] - x[(b*NN + i)*3+1];
        float dz = x[(b*NN + j)*3+2] - x[(b*NN + i)*3+2];
        xnorm_s[t] = sqrtf(dx*dx + dy*dy + dz*dz + EPSV);
    }

    for (int jt = 0; jt < 2; jt++) {
        int j0g = half*128 + jt*64;
        int xb  = jt*64;
        __syncthreads();

        {
            int k = t >> 2, jg = t & 3;
            float ac = acci_s[k], wx = w1x_s[k];
            const float* Arow = &g_AT[(b*HH + k)*NN + j0g];
            #pragma unroll
            for (int q = 0; q < 4; q++) {
                int jl = jg*16 + q*4;
                float4 av = *(const float4*)&Arow[jl];
                float4 xv = *(const float4*)&xnorm_s[xb + jl];
                float4 hv;
                hv.x = silu_f(fmaf(xv.x, wx, av.x + ac));
                hv.y = silu_f(fmaf(xv.y, wx, av.y + ac));
                hv.z = silu_f(fmaf(xv.z, wx, av.z + ac));
                hv.w = silu_f(fmaf(xv.w, wx, av.w + ac));
                *(float4*)&hidT[k*PADJ + jl] = hv;
            }
        }
        __syncthreads();

        float eb[4][4];
        {
            u64 acc2[4][2];
            float4 bv = *(const float4*)&b2[tx*4];
            #pragma unroll
            for (int jj = 0; jj < 4; jj++) {
                acc2[jj][0] = pack2(bv.x, bv.y);
                acc2[jj][1] = pack2(bv.z, bv.w);
            }
            #pragma unroll 4
            for (int kf = 0; kf < 64; kf++) {
                float4 wv = *(const float4*)&w2[kf*HH + tx*4];
                float4 av = *(float4*)&hidT[kf*PADJ + ty*4];
                u64 w01 = pack2(wv.x, wv.y), w23 = pack2(wv.z, wv.w);
                u64 a;
                a = pack2(av.x, av.x); FMA2(acc2[0][0],a,w01); FMA2(acc2[0][1],a,w23);
                a = pack2(av.y, av.y); FMA2(acc2[1][0],a,w01); FMA2(acc2[1][1],a,w23);
                a = pack2(av.z, av.z); FMA2(acc2[2][0],a,w01); FMA2(acc2[2][1],a,w23);
                a = pack2(av.w, av.w); FMA2(acc2[3][0],a,w01); FMA2(acc2[3][1],a,w23);
            }
            #pragma unroll
            for (int jj = 0; jj < 4; jj++) {
                float2 p0 = unpack2(acc2[jj][0]), p1 = unpack2(acc2[jj][1]);
                eb[jj][0] = silu_f(p0.x); eb[jj][1] = silu_f(p0.y);
                eb[jj][2] = silu_f(p1.x); eb[jj][3] = silu_f(p1.y);
            }
        }
        #pragma unroll
        for (int kk = 0; kk < 4; kk++) {
            float4 ev = make_float4(eb[0][kk], eb[1][kk], eb[2][kk], eb[3][kk]);
            *(float4*)&g_eT[(bi*HH + tx*4+kk)*NN + j0g + ty*4] = ev;
        }
        __syncthreads();

        float* sempart = hidT;
        #pragma unroll
        for (int jj = 0; jj < 4; jj++) {
            float p0=0.f, p1=0.f, p2=0.f, p3=0.f;
            #pragma unroll
            for (int kk = 0; kk < 4; kk++) {
                float e = eb[jj][kk];
                const float* swr = &ssw[(tx*4+kk)*4];
                p0 += e*swr[0]; p1 += e*swr[1]; p2 += e*swr[2]; p3 += e*swr[3];
            }
            float* dst = &sempart[(tx*64 + ty*4+jj)*4];
            dst[0]=p0; dst[1]=p1; dst[2]=p2; dst[3]=p3;
        }
        __syncthreads();
        {
            int jl = t >> 2, hd = t & 3;
            float a = ssb[hd];
            #pragma unroll
            for (int r = 0; r < 16; r++) a += sempart[(r*64 + jl)*4 + hd];
            a = (a > 0.f) ? a : 0.2f*a;
            g_sem[(bi*NN + j0g + jl)*HEADS + hd] = a;
        }
    }
}

// ---------------- reductions -------------------------------------------------
__device__ __forceinline__ float warpmaxf(float v){
    #pragma unroll
    for (int s=16;s;s>>=1) v = fmaxf(v, __shfl_xor_sync(0xffffffffu, v, s));
    return v;
}
__device__ __forceinline__ float warpsumf(float v){
    #pragma unroll
    for (int s=16;s;s>>=1) v += __shfl_xor_sync(0xffffffffu, v, s);
    return v;
}
__device__ __forceinline__ float4 blk_reduce4(float4 v, bool is_max, float4* redbuf){
    if (is_max) { v.x=warpmaxf(v.x); v.y=warpmaxf(v.y); v.z=warpmaxf(v.z); v.w=warpmaxf(v.w); }
    else        { v.x=warpsumf(v.x); v.y=warpsumf(v.y); v.z=warpsumf(v.z); v.w=warpsumf(v.w); }
    int w = threadIdx.x>>5, l = threadIdx.x&31;
    if (l == 0) redbuf[w] = v;
    __syncthreads();
    float4 r = redbuf[0];
    #pragma unroll
    for (int q = 1; q < 8; q++) {
        float4 o = redbuf[q];
        if (is_max) { r.x=fmaxf(r.x,o.x); r.y=fmaxf(r.y,o.y); r.z=fmaxf(r.z,o.z); r.w=fmaxf(r.w,o.w); }
        else        { r.x+=o.x; r.y+=o.y; r.z+=o.z; r.w+=o.w; }
    }
    __syncthreads();
    return r;
}
__device__ __forceinline__ float blk_sum256(float v, float* red) {
    int t = threadIdx.x;
    red[t] = v; __syncthreads();
    for (int s = 128; s > 0; s >>= 1) {
        if (t < s) red[t] += red[t + s];
        __syncthreads();
    }
    float r = red[0]; __syncthreads();
    return r;
}

// ---------------- kernel B: fused attention + aggregation -------------------
__global__ __launch_bounds__(256) void attagg_kernel(
        const float* __restrict__ x, const float* __restrict__ vmix,
        const float* __restrict__ log_gamma)
{
    __shared__ float sh_eT[64][132];
    __shared__ float sattT[4][260];
    __shared__ float uT[3][260];
    __shared__ float4 redbuf4[8];

    int bi = blockIdx.x;
    int b = bi >> 8, i = bi & 255;
    int t = threadIdx.x;

    {
        float4 lg = *(const float4*)log_gamma;
        float4 gm = make_float4(__expf(lg.x), __expf(lg.y), __expf(lg.z), __expf(lg.w));
        float dx = x[(b*NN+t)*3+0] - x[(b*NN+i)*3+0];
        float dy = x[(b*NN+t)*3+1] - x[(b*NN+i)*3+1];
        float dz = x[(b*NN+t)*3+2] - x[(b*NN+i)*3+2];
        float xn = sqrtf(dx*dx + dy*dy + dz*dz + EPSV);
        float diag = (t == i) ? INFV : 0.f;
        float xm = xn + diag;

        float4 l1 = make_float4(-xm*gm.x, -xm*gm.y, -xm*gm.z, -xm*gm.w);
        float4 m1 = blk_reduce4(l1, true, redbuf4);
        float4 e1 = make_float4(__expf(l1.x-m1.x), __expf(l1.y-m1.y), __expf(l1.z-m1.z), __expf(l1.w-m1.w));
        float4 s1 = blk_reduce4(e1, false, redbuf4);
        float4 eu = make_float4(__fdividef(e1.x,s1.x), __fdividef(e1.y,s1.y),
                                __fdividef(e1.z,s1.z), __fdividef(e1.w,s1.w));
        float4 sl = *(const float4*)&g_sem[(bi*NN + t)*HEADS];
        sl.x -= diag; sl.y -= diag; sl.z -= diag; sl.w -= diag;
        float4 m2 = blk_reduce4(sl, true, redbuf4);
        float4 e2 = make_float4(__expf(sl.x-m2.x), __expf(sl.y-m2.y), __expf(sl.z-m2.z), __expf(sl.w-m2.w));
        float4 s2 = blk_reduce4(e2, false, redbuf4);
        float4 se = make_float4(__fdividef(e2.x,s2.x), __fdividef(e2.y,s2.y),
                                __fdividef(e2.z,s2.z), __fdividef(e2.w,s2.w));
        float4 p = make_float4(eu.x*se.x, eu.y*se.y, eu.z*se.z, eu.w*se.w);
        float4 m3 = blk_reduce4(p, true, redbuf4);
        float4 e3 = make_float4(__expf(p.x-m3.x), __expf(p.y-m3.y), __expf(p.z-m3.z), __expf(p.w-m3.w));
        float4 s3 = blk_reduce4(e3, false, redbuf4);
        sattT[0][t] = __fdividef(e3.x,s3.x);
        sattT[1][t] = __fdividef(e3.y,s3.y);
        sattT[2][t] = __fdividef(e3.z,s3.z);
        sattT[3][t] = __fdividef(e3.w,s3.w);

        float inv = __fdividef(1.f, xn + EPSV);
        uT[0][t] = dx * inv;
        uT[1][t] = dy * inv;
        uT[2][t] = dz * inv;
    }
    __syncthreads();

    int c = t, hh = c >> 2, hd = c & 3;
    float agg = 0.f, cs0 = 0.f, cs1 = 0.f, cs2 = 0.f;

    for (int ch = 0; ch < 2; ch++) {
        const float* src = &g_eT[bi*HH*NN + ch*128];
        for (int idx = t; idx < 64*32; idx += 256) {
            int hr = idx >> 5, c4 = idx & 31;
            *(float4*)&sh_eT[hr][c4*4] = *(const float4*)&src[hr*NN + c4*4];
        }
        __syncthreads();
        #pragma unroll 4
        for (int q = 0; q < 32; q++) {
            float4 e4 = *(float4*)&sh_eT[hh][q*4];
            float4 a4 = *(float4*)&sattT[hd][ch*128 + q*4];
            float4 u0 = *(float4*)&uT[0][ch*128 + q*4];
            float4 u1 = *(float4*)&uT[1][ch*128 + q*4];
            float4 u2 = *(float4*)&uT[2][ch*128 + q*4];
            float w0 = e4.x*a4.x, w1 = e4.y*a4.y, w2 = e4.z*a4.z, w3 = e4.w*a4.w;
            agg += (w0 + w1) + (w2 + w3);
            cs0 += w0*u0.x + w1*u0.y + w2*u0.z + w3*u0.w;
            cs1 += w0*u1.x + w1*u1.y + w2*u1.z + w3*u1.w;
            cs2 += w0*u2.x + w1*u2.y + w2*u2.z + w3*u2.w;
        }
        __syncthreads();
    }

    const float inv_n = 1.f / (float)NN;
    cs0 *= inv_n; cs1 *= inv_n; cs2 *= inv_n;

    g_hagg[bi*CC + c]     = agg;
    g_combnorm[bi*CC + c] = cs0*cs0 + cs1*cs1 + cs2*cs2;

    float* red = (float*)sh_eT;
    float vm = vmix[c];
    float d0 = blk_sum256(vm * cs0, red);
    float d1 = blk_sum256(vm * cs1, red);
    float d2 = blk_sum256(vm * cs2, red);
    if (c == 0) {
        g_deltav[bi*3 + 0] = d0;
        g_deltav[bi*3 + 1] = d1;
        g_deltav[bi*3 + 2] = d2;
    }
}

// ---------------- kernel C: node MLPs, all weights staged in smem -----------
// grid 128, block 256, ~226KB dynamic smem. One parallel copy phase, then
// 6 MLP phases entirely from shared memory (no global latency in the chain).
// smem float offsets:
#define O_PW1  0        // 16384
#define O_PW2  16384    // 4096
#define O_NW1  20480    // 24576
#define O_NW2  45056    // 4096
#define O_VW1  49152    // 4096
#define O_VW2  53248    // 64
#define O_PB1  53312
#define O_PB2  53376
#define O_NB1  53440
#define O_NB2  53504
#define O_VB1  53568
#define O_CNT  53632    // 1024  cnT[u][node]
#define O_NACT 54656    // 1536  nactT[u][node]
#define O_HID  56192    // 256
#define O_HNEW 56448    // 256
#define O_SBUF 56704    // 1024  [r][node][k]
#define O_MISC 57728    // 12
#define NODE_SMEM_FLOATS 57740

extern __shared__ float sm[];

__global__ __launch_bounds__(256) void node_kernel(
        const float* __restrict__ h, const float* __restrict__ x,
        const float* __restrict__ v,
        const float* __restrict__ pw1, const float* __restrict__ pb1,
        const float* __restrict__ pw2, const float* __restrict__ pb2,
        const float* __restrict__ nw1, const float* __restrict__ nb1,
        const float* __restrict__ nw2, const float* __restrict__ nb2,
        const float* __restrict__ vw1, const float* __restrict__ vb1,
        const float* __restrict__ vw2,
        float* __restrict__ out)
{
    int bi = blockIdx.x;
    int t = threadIdx.x;
    int k = t & 63, r = t >> 6;
    int node = r;

    // ---- stage all weights (independent vectorized loads, high MLP) ----
    #define CP4(dst, src, n) \
        for (int idx = t*4; idx < (n); idx += 1024) \
            *(float4*)&sm[(dst)+idx] = *(const float4*)&(src)[idx];
    CP4(O_PW1, pw1, 16384)
    CP4(O_NW1, nw1, 24576)
    CP4(O_PW2, pw2, 4096)
    CP4(O_NW2, nw2, 4096)
    CP4(O_VW1, vw1, 4096)
    CP4(O_VW2, vw2, 64)
    CP4(O_PB1, pb1, 64)
    CP4(O_PB2, pb2, 64)
    CP4(O_NB1, nb1, 64)
    CP4(O_NB2, nb2, 64)
    CP4(O_VB1, vb1, 64)
    #undef CP4

    // ---- stage activations ----
    #pragma unroll
    for (int q = 0; q < 4; q++) {
        int u = k + q*64;
        sm[O_CNT  + u*4 + node]      = g_combnorm[(bi*4 + node)*CC + u];
        sm[O_NACT + (64+u)*4 + node] = g_hagg[(bi*4 + node)*CC + u];
    }
    sm[O_NACT + k*4 + node] = h[(bi*4 + node)*FF + k];
    __syncthreads();

    // ---- post1: K=256 ----
    {
        float a0=0,a1=0,a2=0,a3=0;
        #pragma unroll 8
        for (int uu = 0; uu < 64; uu++) {
            int u = r*64 + uu;
            float w = sm[O_PW1 + u*HH + k];
            float4 a4 = *(float4*)&sm[O_CNT + u*4];
            a0 += a4.x*w; a1 += a4.y*w; a2 += a4.z*w; a3 += a4.w*w;
        }
        sm[O_SBUF+(r*4+0)*64+k]=a0; sm[O_SBUF+(r*4+1)*64+k]=a1;
        sm[O_SBUF+(r*4+2)*64+k]=a2; sm[O_SBUF+(r*4+3)*64+k]=a3;
    }
    __syncthreads();
    sm[O_HID + k*4+node] = silu_f(sm[O_SBUF+(0*4+node)*64+k] + sm[O_SBUF+(1*4+node)*64+k]
                                + sm[O_SBUF+(2*4+node)*64+k] + sm[O_SBUF+(3*4+node)*64+k]
                                + sm[O_PB1+k]);
    __syncthreads();

    // ---- post2: K=64 ----
    {
        float a0=0,a1=0,a2=0,a3=0;
        #pragma unroll
        for (int uu = 0; uu < 16; uu++) {
            int u = r*16 + uu;
            float w = sm[O_PW2 + u*HH + k];
            float4 a4 = *(float4*)&sm[O_HID + u*4];
            a0 += a4.x*w; a1 += a4.y*w; a2 += a4.z*w; a3 += a4.w*w;
        }
        sm[O_SBUF+(r*4+0)*64+k]=a0; sm[O_SBUF+(r*4+1)*64+k]=a1;
        sm[O_SBUF+(r*4+2)*64+k]=a2; sm[O_SBUF+(r*4+3)*64+k]=a3;
    }
    __syncthreads();
    sm[O_NACT + (320+k)*4+node] = silu_f(sm[O_SBUF+(0*4+node)*64+k] + sm[O_SBUF+(1*4+node)*64+k]
                                       + sm[O_SBUF+(2*4+node)*64+k] + sm[O_SBUF+(3*4+node)*64+k]
                                       + sm[O_PB2+k]);
    __syncthreads();

    // ---- node1: K=384 ----
    {
        float a0=0,a1=0,a2=0,a3=0;
        #pragma unroll 8
        for (int uu = 0; uu < 96; uu++) {
            int u = r*96 + uu;
            float w = sm[O_NW1 + u*HH + k];
            float4 a4 = *(float4*)&sm[O_NACT + u*4];
            a0 += a4.x*w; a1 += a4.y*w; a2 += a4.z*w; a3 += a4.w*w;
        }
        sm[O_SBUF+(r*4+0)*64+k]=a0; sm[O_SBUF+(r*4+1)*64+k]=a1;
        sm[O_SBUF+(r*4+2)*64+k]=a2; sm[O_SBUF+(r*4+3)*64+k]=a3;
    }
    __syncthreads();
    sm[O_HID + k*4+node] = silu_f(sm[O_SBUF+(0*4+node)*64+k] + sm[O_SBUF+(1*4+node)*64+k]
                                + sm[O_SBUF+(2*4+node)*64+k] + sm[O_SBUF+(3*4+node)*64+k]
                                + sm[O_NB1+k]);
    __syncthreads();

    // ---- node2 + residual ----
    {
        float a0=0,a1=0,a2=0,a3=0;
        #pragma unroll
        for (int uu = 0; uu < 16; uu++) {
            int u = r*16 + uu;
            float w = sm[O_NW2 + u*HH + k];
            float4 a4 = *(float4*)&sm[O_HID + u*4];
            a0 += a4.x*w; a1 += a4.y*w; a2 += a4.z*w; a3 += a4.w*w;
        }
        sm[O_SBUF+(r*4+0)*64+k]=a0; sm[O_SBUF+(r*4+1)*64+k]=a1;
        sm[O_SBUF+(r*4+2)*64+k]=a2; sm[O_SBUF+(r*4+3)*64+k]=a3;
    }
    __syncthreads();
    {
        float hn = sm[O_NACT + k*4+node]
                 + silu_f(sm[O_SBUF+(0*4+node)*64+k] + sm[O_SBUF+(1*4+node)*64+k]
                        + sm[O_SBUF+(2*4+node)*64+k] + sm[O_SBUF+(3*4+node)*64+k]
                        + sm[O_NB2+k]);
        sm[O_HNEW + k*4+node] = hn;
        out[(bi*4+node)*FF + k] = hn;
    }
    __syncthreads();

    // ---- vel ----
    {
        float a0=0,a1=0,a2=0,a3=0;
        #pragma unroll
        for (int uu = 0; uu < 16; uu++) {
            int u = r*16 + uu;
            float w = sm[O_VW1 + u*HH + k];
            float4 a4 = *(float4*)&sm[O_HNEW + u*4];
            a0 += a4.x*w; a1 += a4.y*w; a2 += a4.z*w; a3 += a4.w*w;
        }
        sm[O_SBUF+(r*4+0)*64+k]=a0; sm[O_SBUF+(r*4+1)*64+k]=a1;
        sm[O_SBUF+(r*4+2)*64+k]=a2; sm[O_SBUF+(r*4+3)*64+k]=a3;
    }
    __syncthreads();
    {
        float s = sm[O_SBUF+(0*4+node)*64+k] + sm[O_SBUF+(1*4+node)*64+k]
                + sm[O_SBUF+(2*4+node)*64+k] + sm[O_SBUF+(3*4+node)*64+k];
        float sv = silu_f(s + sm[O_VB1+k]) * sm[O_VW2+k];
        sv = warpsumf(sv);
        if ((t & 31) == 0) sm[O_MISC + 4 + (t >> 5)] = sv;   // wbuf[8]
    }
    __syncthreads();
    if (t < 4) sm[O_MISC + t] = sm[O_MISC+4 + t*2] + sm[O_MISC+4 + t*2+1];  // vsc[4]
    __syncthreads();
    if (t < 12) {
        int nd = t / 3, d = t % 3;
        int gi = bi*4 + nd;
        float vv = v[gi*3 + d];
        float vn = g_deltav[gi*3 + d] + sm[O_MISC + nd]*vv;
        out[BB*NN*FF + gi*3 + d]            = x[gi*3 + d] + vn;
        out[BB*NN*FF + BB*NN*3 + gi*3 + d]  = vn;
    }
}

// ---------------------------------------------------------------------------
extern "C" void kernel_launch(void* const* d_in, const int* in_sizes, int n_in,
                              void* d_out, int out_size)
{
    const float* h        = (const float*)d_in[0];
    const float* x        = (const float*)d_in[1];
    const float* v        = (const float*)d_in[2];
    const float* edge_w1  = (const float*)d_in[3];
    const float* edge_b1  = (const float*)d_in[4];
    const float* edge_w2  = (const float*)d_in[5];
    const float* edge_b2  = (const float*)d_in[6];
    const float* sem_w    = (const float*)d_in[7];
    const float* sem_b    = (const float*)d_in[8];
    const float* post_w1  = (const float*)d_in[9];
    const float* post_b1  = (const float*)d_in[10];
    const float* post_w2  = (const float*)d_in[11];
    const float* post_b2  = (const float*)d_in[12];
    const float* node_w1  = (const float*)d_in[13];
    const float* node_b1  = (const float*)d_in[14];
    const float* node_w2  = (const float*)d_in[15];
    const float* node_b2  = (const float*)d_in[16];
    const float* vel_w1   = (const float*)d_in[17];
    const float* vel_b1   = (const float*)d_in[18];
    const float* vel_w2   = (const float*)d_in[19];
    const float* vmix_w   = (const float*)d_in[20];
    const float* log_gamma= (const float*)d_in[21];
    float* out = (float*)d_out;

    static int cfg_done = 0;
    if (!cfg_done) {
        cudaFuncSetAttribute(node_kernel,
                             cudaFuncAttributeMaxDynamicSharedMemorySize,
                             NODE_SMEM_FLOATS * (int)sizeof(float));
        cfg_done = 1;
    }

    pre_kernel<<<BB*NN, 128>>>(h, edge_w1, edge_b1);
    edge_kernel<<<BB*NN*2, 256>>>(x, edge_w1, edge_w2, edge_b2, sem_w, sem_b);
    attagg_kernel<<<BB*NN, 256>>>(x, vmix_w, log_gamma);
    node_kernel<<<BB*NN/4, 256, NODE_SMEM_FLOATS * sizeof(float)>>>(
                                  h, x, v,
                                  post_w1, post_b1, post_w2, post_b2,
                                  node_w1, node_b1, node_w2, node_b2,
                                  vel_w1, vel_b1, vel_w2, out);
}

// round 9
// speedup vs baseline: 4.4191x; 1.0503x over previous
#include <cuda_runtime.h>
#include <math.h>

#define BB 2
#define NN 256
#define FF 64
#define HH 64
#define HEADS 4
#define CC 256
#define EPSV 1e-5f
#define INFV 1e5f
#define PADJ 68

typedef unsigned long long u64;
typedef unsigned int u32;

// ---------------- scratch (device globals) ----------------------------------
__device__ float g_eT[BB*NN*HH*NN];         // [bi][h][j]
__device__ float g_sem[BB*NN*NN*HEADS];
__device__ float g_AT[BB*HH*NN];            // A[b][k][j] = h_j @ W1[0:64]
__device__ float g_acci[BB*NN*HH];          // acci[bi][k] = b1 + h_i @ W1[64:128]
__device__ float g_combnorm[BB*NN*CC];
__device__ float g_hagg[BB*NN*CC];
__device__ float g_deltav[BB*NN*3];

__device__ __forceinline__ float silu_f(float v){ return __fdividef(v, 1.f + __expf(-v)); }

__device__ __forceinline__ u64 pack2(float lo, float hi){
    u64 r; unsigned lu = __float_as_uint(lo), hu = __float_as_uint(hi);
    asm("mov.b64 %0, {%1, %2};" : "=l"(r) : "r"(lu), "r"(hu));
    return r;
}
__device__ __forceinline__ float2 unpack2(u64 v){
    unsigned lu, hu;
    asm("mov.b64 {%0, %1}, %2;" : "=r"(lu), "=r"(hu) : "l"(v));
    return make_float2(__uint_as_float(lu), __uint_as_float(hu));
}
#define FMA2(acc,a,b) asm("fma.rn.f32x2 %0, %1, %2, %3;" : "=l"(acc) : "l"(a), "l"(b), "l"(acc))

__device__ __forceinline__ u32 smem_u32(const void* p){
    u32 a;
    asm("{ .reg .u64 tmp; cvta.to.shared.u64 tmp, %1; cvt.u32.u64 %0, tmp; }"
        : "=r"(a) : "l"(p));
    return a;
}
__device__ __forceinline__ void cpa16(u32 dst, const void* src){
    asm volatile("cp.async.cg.shared.global [%0], [%1], 16;" :: "r"(dst), "l"(src));
}
#define CPA_COMMIT()  asm volatile("cp.async.commit_group;" ::: "memory")
#define CPA_WAIT(N)   asm volatile("cp.async.wait_group %0;" :: "n"(N) : "memory")

// ---------------- kernel P: precompute A and acci ----------------------------
__global__ __launch_bounds__(128) void pre_kernel(
        const float* __restrict__ h, const float* __restrict__ w1,
        const float* __restrict__ b1)
{
    int bi = blockIdx.x;
    int b = bi >> 8, j = bi & 255;
    __shared__ float sh[64];
    int t = threadIdx.x;
    if (t < 64) sh[t] = h[bi*FF + t];
    __syncthreads();
    int k = t & 63;
    const float* wbase = (t < 64) ? w1 : (w1 + 64*HH);
    float a0=0,a1=0,a2=0,a3=0;
    #pragma unroll 8
    for (int f = 0; f < 64; f += 4) {
        a0 += sh[f+0]*__ldg(&wbase[(f+0)*HH + k]);
        a1 += sh[f+1]*__ldg(&wbase[(f+1)*HH + k]);
        a2 += sh[f+2]*__ldg(&wbase[(f+2)*HH + k]);
        a3 += sh[f+3]*__ldg(&wbase[(f+3)*HH + k]);
    }
    float a = (a0+a1)+(a2+a3);
    if (t < 64) g_AT[(b*HH + k)*NN + j] = a;
    else        g_acci[bi*HH + k] = a + b1[k];
}

// ---------------- kernel A: edge layer2 + sem -------------------------------
__global__ __launch_bounds__(256) void edge_kernel(
        const float* __restrict__ x,
        const float* __restrict__ w1,
        const float* __restrict__ w2, const float* __restrict__ b2,
        const float* __restrict__ sw, const float* __restrict__ sb)
{
    int blk = blockIdx.x;
    int bi = blk >> 1, half = blk & 1;
    int b = bi >> 8, i = bi & 255;
    int t = threadIdx.x;
    int tx = t & 15, ty = t >> 4;

    __shared__ float hidT[64*PADJ];
    __shared__ float acci_s[64];
    __shared__ float w1x_s[64];
    __shared__ float xnorm_s[128];
    __shared__ float ssw[256];
    __shared__ float ssb[4];

    if (t < 64) { acci_s[t] = g_acci[bi*HH + t]; w1x_s[t] = w1[128*HH + t]; }
    ssw[t] = sw[t];
    if (t < 4) ssb[t] = sb[t];
    if (t < 128) {
        int j = half*128 + t;
        float dx = x[(b*NN + j)*3+0] - x[(b*NN + i)*3+0];
        float dy = x[(b*NN + j)*3+1] - x[(b*NN + i)*3+1];
        float dz = x[(b*NN + j)*3+2] - x[(b*NN + i)*3+2];
        xnorm_s[t] = sqrtf(dx*dx + dy*dy + dz*dz + EPSV);
    }

    for (int jt = 0; jt < 2; jt++) {
        int j0g = half*128 + jt*64;
        int xb  = jt*64;
        __syncthreads();

        {
            int k = t >> 2, jg = t & 3;
            float ac = acci_s[k], wx = w1x_s[k];
            const float* Arow = &g_AT[(b*HH + k)*NN + j0g];
            #pragma unroll
            for (int q = 0; q < 4; q++) {
                int jl = jg*16 + q*4;
                float4 av = *(const float4*)&Arow[jl];
                float4 xv = *(const float4*)&xnorm_s[xb + jl];
                float4 hv;
                hv.x = silu_f(fmaf(xv.x, wx, av.x + ac));
                hv.y = silu_f(fmaf(xv.y, wx, av.y + ac));
                hv.z = silu_f(fmaf(xv.z, wx, av.z + ac));
                hv.w = silu_f(fmaf(xv.w, wx, av.w + ac));
                *(float4*)&hidT[k*PADJ + jl] = hv;
            }
        }
        __syncthreads();

        float eb[4][4];
        {
            u64 acc2[4][2];
            float4 bv = *(const float4*)&b2[tx*4];
            #pragma unroll
            for (int jj = 0; jj < 4; jj++) {
                acc2[jj][0] = pack2(bv.x, bv.y);
                acc2[jj][1] = pack2(bv.z, bv.w);
            }
            #pragma unroll 4
            for (int kf = 0; kf < 64; kf++) {
                float4 wv = *(const float4*)&w2[kf*HH + tx*4];
                float4 av = *(float4*)&hidT[kf*PADJ + ty*4];
                u64 w01 = pack2(wv.x, wv.y), w23 = pack2(wv.z, wv.w);
                u64 a;
                a = pack2(av.x, av.x); FMA2(acc2[0][0],a,w01); FMA2(acc2[0][1],a,w23);
                a = pack2(av.y, av.y); FMA2(acc2[1][0],a,w01); FMA2(acc2[1][1],a,w23);
                a = pack2(av.z, av.z); FMA2(acc2[2][0],a,w01); FMA2(acc2[2][1],a,w23);
                a = pack2(av.w, av.w); FMA2(acc2[3][0],a,w01); FMA2(acc2[3][1],a,w23);
            }
            #pragma unroll
            for (int jj = 0; jj < 4; jj++) {
                float2 p0 = unpack2(acc2[jj][0]), p1 = unpack2(acc2[jj][1]);
                eb[jj][0] = silu_f(p0.x); eb[jj][1] = silu_f(p0.y);
                eb[jj][2] = silu_f(p1.x); eb[jj][3] = silu_f(p1.y);
            }
        }
        #pragma unroll
        for (int kk = 0; kk < 4; kk++) {
            float4 ev = make_float4(eb[0][kk], eb[1][kk], eb[2][kk], eb[3][kk]);
            *(float4*)&g_eT[(bi*HH + tx*4+kk)*NN + j0g + ty*4] = ev;
        }
        __syncthreads();

        float* sempart = hidT;
        #pragma unroll
        for (int jj = 0; jj < 4; jj++) {
            float p0=0.f, p1=0.f, p2=0.f, p3=0.f;
            #pragma unroll
            for (int kk = 0; kk < 4; kk++) {
                float e = eb[jj][kk];
                const float* swr = &ssw[(tx*4+kk)*4];
                p0 += e*swr[0]; p1 += e*swr[1]; p2 += e*swr[2]; p3 += e*swr[3];
            }
            float* dst = &sempart[(tx*64 + ty*4+jj)*4];
            dst[0]=p0; dst[1]=p1; dst[2]=p2; dst[3]=p3;
        }
        __syncthreads();
        {
            int jl = t >> 2, hd = t & 3;
            float a = ssb[hd];
            #pragma unroll
            for (int r = 0; r < 16; r++) a += sempart[(r*64 + jl)*4 + hd];
            a = (a > 0.f) ? a : 0.2f*a;
            g_sem[(bi*NN + j0g + jl)*HEADS + hd] = a;
        }
    }
}

// ---------------- reductions -------------------------------------------------
__device__ __forceinline__ float warpmaxf(float v){
    #pragma unroll
    for (int s=16;s;s>>=1) v = fmaxf(v, __shfl_xor_sync(0xffffffffu, v, s));
    return v;
}
__device__ __forceinline__ float warpsumf(float v){
    #pragma unroll
    for (int s=16;s;s>>=1) v += __shfl_xor_sync(0xffffffffu, v, s);
    return v;
}
__device__ __forceinline__ float4 blk_reduce4(float4 v, bool is_max, float4* redbuf){
    if (is_max) { v.x=warpmaxf(v.x); v.y=warpmaxf(v.y); v.z=warpmaxf(v.z); v.w=warpmaxf(v.w); }
    else        { v.x=warpsumf(v.x); v.y=warpsumf(v.y); v.z=warpsumf(v.z); v.w=warpsumf(v.w); }
    int w = threadIdx.x>>5, l = threadIdx.x&31;
    if (l == 0) redbuf[w] = v;
    __syncthreads();
    float4 r = redbuf[0];
    #pragma unroll
    for (int q = 1; q < 8; q++) {
        float4 o = redbuf[q];
        if (is_max) { r.x=fmaxf(r.x,o.x); r.y=fmaxf(r.y,o.y); r.z=fmaxf(r.z,o.z); r.w=fmaxf(r.w,o.w); }
        else        { r.x+=o.x; r.y+=o.y; r.z+=o.z; r.w+=o.w; }
    }
    __syncthreads();
    return r;
}
__device__ __forceinline__ float blk_sum256(float v, float* red) {
    int t = threadIdx.x;
    red[t] = v; __syncthreads();
    for (int s = 128; s > 0; s >>= 1) {
        if (t < s) red[t] += red[t + s];
        __syncthreads();
    }
    float r = red[0]; __syncthreads();
    return r;
}

// ---------------- kernel B: fused attention + aggregation -------------------
__global__ __launch_bounds__(256) void attagg_kernel(
        const float* __restrict__ x, const float* __restrict__ vmix,
        const float* __restrict__ log_gamma)
{
    __shared__ float sh_eT[64][132];
    __shared__ float sattT[4][260];
    __shared__ float uT[3][260];
    __shared__ float4 redbuf4[8];

    int bi = blockIdx.x;
    int b = bi >> 8, i = bi & 255;
    int t = threadIdx.x;

    {
        float4 lg = *(const float4*)log_gamma;
        float4 gm = make_float4(__expf(lg.x), __expf(lg.y), __expf(lg.z), __expf(lg.w));
        float dx = x[(b*NN+t)*3+0] - x[(b*NN+i)*3+0];
        float dy = x[(b*NN+t)*3+1] - x[(b*NN+i)*3+1];
        float dz = x[(b*NN+t)*3+2] - x[(b*NN+i)*3+2];
        float xn = sqrtf(dx*dx + dy*dy + dz*dz + EPSV);
        float diag = (t == i) ? INFV : 0.f;
        float xm = xn + diag;

        float4 l1 = make_float4(-xm*gm.x, -xm*gm.y, -xm*gm.z, -xm*gm.w);
        float4 m1 = blk_reduce4(l1, true, redbuf4);
        float4 e1 = make_float4(__expf(l1.x-m1.x), __expf(l1.y-m1.y), __expf(l1.z-m1.z), __expf(l1.w-m1.w));
        float4 s1 = blk_reduce4(e1, false, redbuf4);
        float4 eu = make_float4(__fdividef(e1.x,s1.x), __fdividef(e1.y,s1.y),
                                __fdividef(e1.z,s1.z), __fdividef(e1.w,s1.w));
        float4 sl = *(const float4*)&g_sem[(bi*NN + t)*HEADS];
        sl.x -= diag; sl.y -= diag; sl.z -= diag; sl.w -= diag;
        float4 m2 = blk_reduce4(sl, true, redbuf4);
        float4 e2 = make_float4(__expf(sl.x-m2.x), __expf(sl.y-m2.y), __expf(sl.z-m2.z), __expf(sl.w-m2.w));
        float4 s2 = blk_reduce4(e2, false, redbuf4);
        float4 se = make_float4(__fdividef(e2.x,s2.x), __fdividef(e2.y,s2.y),
                                __fdividef(e2.z,s2.z), __fdividef(e2.w,s2.w));
        float4 p = make_float4(eu.x*se.x, eu.y*se.y, eu.z*se.z, eu.w*se.w);
        float4 m3 = blk_reduce4(p, true, redbuf4);
        float4 e3 = make_float4(__expf(p.x-m3.x), __expf(p.y-m3.y), __expf(p.z-m3.z), __expf(p.w-m3.w));
        float4 s3 = blk_reduce4(e3, false, redbuf4);
        sattT[0][t] = __fdividef(e3.x,s3.x);
        sattT[1][t] = __fdividef(e3.y,s3.y);
        sattT[2][t] = __fdividef(e3.z,s3.z);
        sattT[3][t] = __fdividef(e3.w,s3.w);

        float inv = __fdividef(1.f, xn + EPSV);
        uT[0][t] = dx * inv;
        uT[1][t] = dy * inv;
        uT[2][t] = dz * inv;
    }
    __syncthreads();

    int c = t, hh = c >> 2, hd = c & 3;
    float agg = 0.f, cs0 = 0.f, cs1 = 0.f, cs2 = 0.f;

    for (int ch = 0; ch < 2; ch++) {
        const float* src = &g_eT[bi*HH*NN + ch*128];
        for (int idx = t; idx < 64*32; idx += 256) {
            int hr = idx >> 5, c4 = idx & 31;
            *(float4*)&sh_eT[hr][c4*4] = *(const float4*)&src[hr*NN + c4*4];
        }
        __syncthreads();
        #pragma unroll 4
        for (int q = 0; q < 32; q++) {
            float4 e4 = *(float4*)&sh_eT[hh][q*4];
            float4 a4 = *(float4*)&sattT[hd][ch*128 + q*4];
            float4 u0 = *(float4*)&uT[0][ch*128 + q*4];
            float4 u1 = *(float4*)&uT[1][ch*128 + q*4];
            float4 u2 = *(float4*)&uT[2][ch*128 + q*4];
            float w0 = e4.x*a4.x, w1 = e4.y*a4.y, w2 = e4.z*a4.z, w3 = e4.w*a4.w;
            agg += (w0 + w1) + (w2 + w3);
            cs0 += w0*u0.x + w1*u0.y + w2*u0.z + w3*u0.w;
            cs1 += w0*u1.x + w1*u1.y + w2*u1.z + w3*u1.w;
            cs2 += w0*u2.x + w1*u2.y + w2*u2.z + w3*u2.w;
        }
        __syncthreads();
    }

    const float inv_n = 1.f / (float)NN;
    cs0 *= inv_n; cs1 *= inv_n; cs2 *= inv_n;

    g_hagg[bi*CC + c]     = agg;
    g_combnorm[bi*CC + c] = cs0*cs0 + cs1*cs1 + cs2*cs2;

    float* red = (float*)sh_eT;
    float vm = vmix[c];
    float d0 = blk_sum256(vm * cs0, red);
    float d1 = blk_sum256(vm * cs1, red);
    float d2 = blk_sum256(vm * cs2, red);
    if (c == 0) {
        g_deltav[bi*3 + 0] = d0;
        g_deltav[bi*3 + 1] = d1;
        g_deltav[bi*3 + 2] = d2;
    }
}

// ---------------- kernel C: node MLPs — cp.async pipelined staging ----------
// grid 128, block 512. Weight groups staged via cp.async; each phase waits
// only for its own group (nw1's 96KB hidden behind post1+post2).
#define O_PW1  0        // 16384
#define O_PW2  16384    // 4096
#define O_NW1  20480    // 24576
#define O_NW2  45056    // 4096
#define O_PB1  49152
#define O_PB2  49216
#define O_NB1  49280
#define O_NB2  49344
#define O_CNT  49408    // 1024
#define O_NACT 50432    // 1536
#define O_HID  51968    // 256
#define O_HNEW 52224    // 256
#define O_SBUF 52480    // 2048  [r(8)][node(4)][k(64)]
#define O_MISC 54528    // 16
#define NODE_SMEM_FLOATS 54544

extern __shared__ float sm[];

__global__ __launch_bounds__(512) void node_kernel(
        const float* __restrict__ h, const float* __restrict__ x,
        const float* __restrict__ v,
        const float* __restrict__ pw1, const float* __restrict__ pb1,
        const float* __restrict__ pw2, const float* __restrict__ pb2,
        const float* __restrict__ nw1, const float* __restrict__ nb1,
        const float* __restrict__ nw2, const float* __restrict__ nb2,
        const float* __restrict__ vw1, const float* __restrict__ vb1,
        const float* __restrict__ vw2,
        float* __restrict__ out)
{
    int bi = blockIdx.x;
    int t = threadIdx.x;
    int k = t & 63, r = t >> 6;   // r: 0..7
    u32 smb = smem_u32(sm);

    // ---- group 0: pw1 + pb1 ----
    for (int idx = t*16; idx < 65536; idx += 512*16)
        cpa16(smb + O_PW1*4 + idx, (const char*)pw1 + idx);
    if (t < 16) cpa16(smb + O_PB1*4 + t*16, (const char*)pb1 + t*16);
    CPA_COMMIT();
    // ---- group 1: pw2 + pb2 ----
    for (int idx = t*16; idx < 16384; idx += 512*16)
        cpa16(smb + O_PW2*4 + idx, (const char*)pw2 + idx);
    if (t < 16) cpa16(smb + O_PB2*4 + t*16, (const char*)pb2 + t*16);
    CPA_COMMIT();
    // ---- group 2: nw1 + nb1 ----
    for (int idx = t*16; idx < 98304; idx += 512*16)
        cpa16(smb + O_NW1*4 + idx, (const char*)nw1 + idx);
    if (t < 16) cpa16(smb + O_NB1*4 + t*16, (const char*)nb1 + t*16);
    CPA_COMMIT();
    // ---- group 3: nw2 + nb2 ----
    for (int idx = t*16; idx < 16384; idx += 512*16)
        cpa16(smb + O_NW2*4 + idx, (const char*)nw2 + idx);
    if (t < 16) cpa16(smb + O_NB2*4 + t*16, (const char*)nb2 + t*16);
    CPA_COMMIT();

    // ---- stage activations (regular loads; overlap cp.async in flight) ----
    if (t < 256) {
        int kk = t & 63, node = t >> 6;
        #pragma unroll
        for (int q = 0; q < 4; q++) {
            int u = kk + q*64;
            sm[O_CNT  + u*4 + node]      = g_combnorm[(bi*4 + node)*CC + u];
            sm[O_NACT + (64+u)*4 + node] = g_hagg[(bi*4 + node)*CC + u];
        }
        sm[O_NACT + kk*4 + node] = h[(bi*4 + node)*FF + kk];
    }

    CPA_WAIT(3);            // pw1/pb1 resident
    __syncthreads();

    // ---- post1: K=256, 8-way split ----
    {
        float a0=0,a1=0,a2=0,a3=0;
        #pragma unroll 8
        for (int uu = 0; uu < 32; uu++) {
            int u = r*32 + uu;
            float w = sm[O_PW1 + u*HH + k];
            float4 a4 = *(float4*)&sm[O_CNT + u*4];
            a0 += a4.x*w; a1 += a4.y*w; a2 += a4.z*w; a3 += a4.w*w;
        }
        sm[O_SBUF+(r*4+0)*64+k]=a0; sm[O_SBUF+(r*4+1)*64+k]=a1;
        sm[O_SBUF+(r*4+2)*64+k]=a2; sm[O_SBUF+(r*4+3)*64+k]=a3;
    }
    CPA_WAIT(2);            // pw2 resident (for next phase)
    __syncthreads();
    if (t < 256) {
        int kk = t & 63, node = t >> 6;
        float s = sm[O_PB1+kk];
        #pragma unroll
        for (int q = 0; q < 8; q++) s += sm[O_SBUF+(q*4+node)*64+kk];
        sm[O_HID + kk*4+node] = silu_f(s);
    }
    __syncthreads();

    // ---- post2: K=64 ----
    {
        float a0=0,a1=0,a2=0,a3=0;
        #pragma unroll
        for (int uu = 0; uu < 8; uu++) {
            int u = r*8 + uu;
            float w = sm[O_PW2 + u*HH + k];
            float4 a4 = *(float4*)&sm[O_HID + u*4];
            a0 += a4.x*w; a1 += a4.y*w; a2 += a4.z*w; a3 += a4.w*w;
        }
        sm[O_SBUF+(r*4+0)*64+k]=a0; sm[O_SBUF+(r*4+1)*64+k]=a1;
        sm[O_SBUF+(r*4+2)*64+k]=a2; sm[O_SBUF+(r*4+3)*64+k]=a3;
    }
    CPA_WAIT(1);            // nw1 resident
    __syncthreads();
    if (t < 256) {
        int kk = t & 63, node = t >> 6;
        float s = sm[O_PB2+kk];
        #pragma unroll
        for (int q = 0; q < 8; q++) s += sm[O_SBUF+(q*4+node)*64+kk];
        sm[O_NACT + (320+kk)*4+node] = silu_f(s);
    }
    __syncthreads();

    // ---- node1: K=384 ----
    {
        float a0=0,a1=0,a2=0,a3=0;
        #pragma unroll 8
        for (int uu = 0; uu < 48; uu++) {
            int u = r*48 + uu;
            float w = sm[O_NW1 + u*HH + k];
            float4 a4 = *(float4*)&sm[O_NACT + u*4];
            a0 += a4.x*w; a1 += a4.y*w; a2 += a4.z*w; a3 += a4.w*w;
        }
        sm[O_SBUF+(r*4+0)*64+k]=a0; sm[O_SBUF+(r*4+1)*64+k]=a1;
        sm[O_SBUF+(r*4+2)*64+k]=a2; sm[O_SBUF+(r*4+3)*64+k]=a3;
    }
    CPA_WAIT(0);            // nw2 resident
    __syncthreads();
    if (t < 256) {
        int kk = t & 63, node = t >> 6;
        float s = sm[O_NB1+kk];
        #pragma unroll
        for (int q = 0; q < 8; q++) s += sm[O_SBUF+(q*4+node)*64+kk];
        sm[O_HID + kk*4+node] = silu_f(s);
    }
    __syncthreads();

    // ---- node2 + residual ----
    {
        float a0=0,a1=0,a2=0,a3=0;
        #pragma unroll
        for (int uu = 0; uu < 8; uu++) {
            int u = r*8 + uu;
            float w = sm[O_NW2 + u*HH + k];
            float4 a4 = *(float4*)&sm[O_HID + u*4];
            a0 += a4.x*w; a1 += a4.y*w; a2 += a4.z*w; a3 += a4.w*w;
        }
        sm[O_SBUF+(r*4+0)*64+k]=a0; sm[O_SBUF+(r*4+1)*64+k]=a1;
        sm[O_SBUF+(r*4+2)*64+k]=a2; sm[O_SBUF+(r*4+3)*64+k]=a3;
    }
    __syncthreads();
    if (t < 256) {
        int kk = t & 63, node = t >> 6;
        float s = sm[O_NB2+kk];
        #pragma unroll
        for (int q = 0; q < 8; q++) s += sm[O_SBUF+(q*4+node)*64+kk];
        float hn = sm[O_NACT + kk*4+node] + silu_f(s);
        sm[O_HNEW + kk*4+node] = hn;
        out[(bi*4+node)*FF + kk] = hn;
    }
    __syncthreads();

    // ---- vel: K=64, weights from global (8 independent LDGs/thread) ----
    {
        float a0=0,a1=0,a2=0,a3=0;
        #pragma unroll
        for (int uu = 0; uu < 8; uu++) {
            int u = r*8 + uu;
            float w = __ldg(&vw1[u*HH + k]);
            float4 a4 = *(float4*)&sm[O_HNEW + u*4];
            a0 += a4.x*w; a1 += a4.y*w; a2 += a4.z*w; a3 += a4.w*w;
        }
        sm[O_SBUF+(r*4+0)*64+k]=a0; sm[O_SBUF+(r*4+1)*64+k]=a1;
        sm[O_SBUF+(r*4+2)*64+k]=a2; sm[O_SBUF+(r*4+3)*64+k]=a3;
    }
    __syncthreads();
    if (t < 256) {
        int kk = t & 63, node = t >> 6;
        float s = 0.f;
        #pragma unroll
        for (int q = 0; q < 8; q++) s += sm[O_SBUF+(q*4+node)*64+kk];
        float sv = silu_f(s + __ldg(&vb1[kk])) * __ldg(&vw2[kk]);
        sv = warpsumf(sv);
        if ((t & 31) == 0) sm[O_MISC + 4 + (t >> 5)] = sv;   // wbuf[8]
    }
    __syncthreads();
    if (t < 4) sm[O_MISC + t] = sm[O_MISC+4 + t*2] + sm[O_MISC+4 + t*2+1];
    __syncthreads();
    if (t < 12) {
        int nd = t / 3, d = t % 3;
        int gi = bi*4 + nd;
        float vv = v[gi*3 + d];
        float vn = g_deltav[gi*3 + d] + sm[O_MISC + nd]*vv;
        out[BB*NN*FF + gi*3 + d]            = x[gi*3 + d] + vn;
        out[BB*NN*FF + BB*NN*3 + gi*3 + d]  = vn;
    }
}

// ---------------------------------------------------------------------------
extern "C" void kernel_launch(void* const* d_in, const int* in_sizes, int n_in,
                              void* d_out, int out_size)
{
    const float* h        = (const float*)d_in[0];
    const float* x        = (const float*)d_in[1];
    const float* v        = (const float*)d_in[2];
    const float* edge_w1  = (const float*)d_in[3];
    const float* edge_b1  = (const float*)d_in[4];
    const float* edge_w2  = (const float*)d_in[5];
    const float* edge_b2  = (const float*)d_in[6];
    const float* sem_w    = (const float*)d_in[7];
    const float* sem_b    = (const float*)d_in[8];
    const float* post_w1  = (const float*)d_in[9];
    const float* post_b1  = (const float*)d_in[10];
    const float* post_w2  = (const float*)d_in[11];
    const float* post_b2  = (const float*)d_in[12];
    const float* node_w1  = (const float*)d_in[13];
    const float* node_b1  = (const float*)d_in[14];
    const float* node_w2  = (const float*)d_in[15];
    const float* node_b2  = (const float*)d_in[16];
    const float* vel_w1   = (const float*)d_in[17];
    const float* vel_b1   = (const float*)d_in[18];
    const float* vel_w2   = (const float*)d_in[19];
    const float* vmix_w   = (const float*)d_in[20];
    const float* log_gamma= (const float*)d_in[21];
    float* out = (float*)d_out;

    static int cfg_done = 0;
    if (!cfg_done) {
        cudaFuncSetAttribute(node_kernel,
                             cudaFuncAttributeMaxDynamicSharedMemorySize,
                             NODE_SMEM_FLOATS * (int)sizeof(float));
        cfg_done = 1;
    }

    pre_kernel<<<BB*NN, 128>>>(h, edge_w1, edge_b1);
    edge_kernel<<<BB*NN*2, 256>>>(x, edge_w1, edge_w2, edge_b2, sem_w, sem_b);
    attagg_kernel<<<BB*NN, 256>>>(x, vmix_w, log_gamma);
    node_kernel<<<BB*NN/4, 512, NODE_SMEM_FLOATS * sizeof(float)>>>(
                                  h, x, v,
                                  post_w1, post_b1, post_w2, post_b2,
                                  node_w1, node_b1, node_w2, node_b2,
                                  vel_w1, vel_b1, vel_w2, out);
}